// round 10
// baseline (speedup 1.0000x reference)
#include <cuda_runtime.h>
#include <cuda_bf16.h>
#include <cuda_fp16.h>
#include <math.h>
#include <stdint.h>

#define N_NODES 100000
#define N_EDGES 3200000
#define CSR_BLOCKS 512

// ---------------- scratch (static __device__, no allocation) ----------------
__device__ int   g_bar;
__device__ int   g_bsum[CSR_BLOCKS];
__device__ int   g_cnt[N_NODES];
__device__ int   g_rowptr[N_NODES + 1];
__device__ int   g_cursor[N_NODES];
__device__ int   g_col[N_EDGES];
__device__ float g_dinv[N_NODES];
__device__ __align__(16) __half g_W1h[128 * 256];   // [n][k] concat W1|Ws02|Ws03 (transposed), fp16
__device__ __align__(16) __half g_W2h[64 * 64];     // [n][k] concat W2|Ws13 (transposed), fp16
__device__ __align__(16) __half g_hs1h[N_NODES * 64];  // fp16: dinv * (x @ W1)
__device__ __align__(16) float  g_s02[N_NODES * 32];   // x @ Ws02
__device__ __align__(16) float  g_s03[N_NODES * 16];   // x @ Ws03
__device__ __align__(16) __half g_x1h[N_NODES * 64];   // fp16 x1
__device__ __align__(16) __half g_hs2h[N_NODES * 32];  // fp16: dinv * (x1 @ W2)
__device__ __align__(16) float  g_s13[N_NODES * 16];   // x1 @ Ws13
__device__ __align__(16) __half g_x2h[N_NODES * 32];   // fp16 x2
__device__ __align__(16) __half g_hs3h[N_NODES * 16];  // fp16: dinv * (x2 @ W3)

// ---------------- helpers ----------------
__device__ __forceinline__ uint32_t smem_u32(const void* p) {
    uint32_t a;
    asm("{ .reg .u64 t; cvta.to.shared.u64 t, %1; cvt.u32.u64 %0, t; }" : "=r"(a) : "l"(p));
    return a;
}

#define SW128(o) ((uint32_t)(o) ^ ((((uint32_t)(o)) >> 3) & 0x70u))

__device__ __forceinline__ void ldsm_x4(uint32_t addr, uint32_t* r) {
    asm volatile("ldmatrix.sync.aligned.m8n8.x4.shared.b16 {%0,%1,%2,%3}, [%4];"
                 : "=r"(r[0]), "=r"(r[1]), "=r"(r[2]), "=r"(r[3]) : "r"(addr));
}

// fp16 x fp16 -> fp32 accumulate
__device__ __forceinline__ void mma16816h(float* c, const uint32_t* a, const uint32_t* b) {
    asm volatile(
        "mma.sync.aligned.m16n8k16.row.col.f32.f16.f16.f32 "
        "{%0,%1,%2,%3}, {%4,%5,%6,%7}, {%8,%9}, {%0,%1,%2,%3};"
        : "+f"(c[0]), "+f"(c[1]), "+f"(c[2]), "+f"(c[3])
        : "r"(a[0]), "r"(a[1]), "r"(a[2]), "r"(a[3]), "r"(b[0]), "r"(b[1]));
}

__device__ __forceinline__ uint32_t pk_h2(__half a, __half b) {
    __half2 t;
    t.x = a; t.y = b;
    return *reinterpret_cast<uint32_t*>(&t);
}

__device__ __forceinline__ void acc_u4(float* f, uint4 v) {
    float2 p;
    p = __half22float2(*reinterpret_cast<__half2*>(&v.x)); f[0] += p.x; f[1] += p.y;
    p = __half22float2(*reinterpret_cast<__half2*>(&v.y)); f[2] += p.x; f[3] += p.y;
    p = __half22float2(*reinterpret_cast<__half2*>(&v.z)); f[4] += p.x; f[5] += p.y;
    p = __half22float2(*reinterpret_cast<__half2*>(&v.w)); f[6] += p.x; f[7] += p.y;
}

// ---------------- fused CSR build (persistent grid, atomic barriers) ----------------
__device__ __forceinline__ int ld_acquire(const int* p) {
    int v;
    asm volatile("ld.acquire.gpu.b32 %0, [%1];" : "=r"(v) : "l"(p));
    return v;
}

__device__ __forceinline__ void grid_bar(int target) {
    __syncthreads();
    if (threadIdx.x == 0) {
        __threadfence();
        atomicAdd(&g_bar, 1);
        while (ld_acquire(&g_bar) < target) __nanosleep(256);
    }
    __syncthreads();
}

__global__ __launch_bounds__(256, 4) void k_csr(const int* __restrict__ src,
                                               const int* __restrict__ dst) {
    const int B = CSR_BLOCKS;
    int tid = threadIdx.x, b = blockIdx.x;
    int gthreads = B * 256;
    int gt = b * 256 + tid;
    __shared__ int sm[256];

    // P1: degree count
    for (int e = gt; e < N_EDGES; e += gthreads)
        atomicAdd(&g_cnt[dst[e]], 1);
    grid_bar(B);

    // P2a: per-block partial sum over node chunk
    const int CH = (N_NODES + B - 1) / B;          // 196
    int nb = b * CH;
    int ne = nb + CH; if (ne > N_NODES) ne = N_NODES;
    int s = 0;
    for (int i = nb + tid; i < ne; i += 256) s += g_cnt[i];
    sm[tid] = s;
    __syncthreads();
    for (int off = 128; off > 0; off >>= 1) {
        if (tid < off) sm[tid] += sm[tid + off];
        __syncthreads();
    }
    if (tid == 0) g_bsum[b] = sm[0];
    grid_bar(2 * B);

    // P2b: block 0 exclusive-scans the 512 partials
    if (b == 0) {
        int i0 = 2 * tid, i1 = 2 * tid + 1;
        int v0 = (i0 < B) ? g_bsum[i0] : 0;
        int v1 = (i1 < B) ? g_bsum[i1] : 0;
        int tsum = v0 + v1;
        __syncthreads();
        sm[tid] = tsum;
        __syncthreads();
        for (int off = 1; off < 256; off <<= 1) {
            int x = (tid >= off) ? sm[tid - off] : 0;
            __syncthreads();
            sm[tid] += x;
            __syncthreads();
        }
        int run = (tid == 0) ? 0 : sm[tid - 1];
        if (i0 < B) g_bsum[i0] = run;
        run += v0;
        if (i1 < B) g_bsum[i1] = run;
        if (tid == 255) g_rowptr[N_NODES] = sm[255];
    }
    grid_bar(3 * B);

    // P2c: write rowptr/cursor/dinv for this block's chunk (CH=196 <= 256)
    {
        int cnt_n = ne - nb;
        int myc = 0;
        if (tid < cnt_n) myc = g_cnt[nb + tid];
        __syncthreads();
        sm[tid] = myc;
        __syncthreads();
        for (int off = 1; off < 256; off <<= 1) {
            int x = (tid >= off) ? sm[tid - off] : 0;
            __syncthreads();
            sm[tid] += x;
            __syncthreads();
        }
        if (tid < cnt_n) {
            int run = g_bsum[b] + ((tid == 0) ? 0 : sm[tid - 1]);
            g_rowptr[nb + tid] = run;
            g_cursor[nb + tid] = run;
            g_dinv[nb + tid] = rsqrtf((float)myc + 1.0f);
        }
    }
    grid_bar(4 * B);

    // P3: fill (cursor clamp protects against profiler kernel-replay state corruption)
    for (int e = gt; e < N_EDGES; e += gthreads) {
        int d = dst[e];
        int p = atomicAdd(&g_cursor[d], 1);
        if (p < N_EDGES) g_col[p] = src[e];
    }
}

// ---------------- weight packing ([n][k] transposed, fp16) ----------------
__global__ void k_pack1(const float* __restrict__ W1, const float* __restrict__ Ws02,
                        const float* __restrict__ Ws03) {
    int i = blockIdx.x * 256 + threadIdx.x;
    if (i >= 128 * 256) return;
    int n = i >> 8, k = i & 255;
    float v = 0.f;
    if (n < 64)       v = W1[k * 64 + n];
    else if (n < 96)  v = Ws02[k * 32 + (n - 64)];
    else if (n < 112) v = Ws03[k * 16 + (n - 96)];
    g_W1h[i] = __float2half(v);
}

__global__ void k_pack2(const float* __restrict__ W2, const float* __restrict__ Ws13) {
    int i = blockIdx.x * 256 + threadIdx.x;
    if (i >= 64 * 64) return;
    int n = i >> 6, k = i & 63;
    float v = 0.f;
    if (n < 32)      v = W2[k * 32 + n];
    else if (n < 48) v = Ws13[k * 16 + (n - 32)];
    g_W2h[i] = __float2half(v);
}

// ---------------- GEMM1 (mma.sync fp16 single-plane): x[100k,256] @ Wcat1[256,128] ----------------
// CTA: 128 rows x 128 cols, K in 4 chunks of 64. 8 warps as 4(m) x 2(n); warp tile 32x64.
#define G1_A 0
#define G1_B 16384
#define G1_TOTAL 32768

__global__ __launch_bounds__(256, 2) void k_gemm1_mma(const float* __restrict__ X) {
    extern __shared__ __align__(1024) char smem[];
    uint32_t sb = smem_u32(smem);
    int tid = threadIdx.x, wid = tid >> 5, lane = tid & 31;
    int rowBase = blockIdx.x * 128;
    int mw = wid >> 1, nw = wid & 1;          // 4 m-warps x 2 n-warps
    int g = lane >> 2, t4 = lane & 3;

    float c[2][8][4];
    #pragma unroll
    for (int a = 0; a < 2; a++)
        #pragma unroll
        for (int b = 0; b < 8; b++)
            #pragma unroll
            for (int d = 0; d < 4; d++) c[a][b][d] = 0.f;

    int lr = lane & 7, lts = lane >> 3;
    int aRow = tid >> 4, aKq = (tid & 15) * 4;

    for (int ch = 0; ch < 4; ch++) {
        int kt = ch * 64;
        // prefetch A chunk (overlaps previous MMA phase)
        float4 v[8];
        #pragma unroll
        for (int i = 0; i < 8; i++) {
            int row = aRow + i * 16;
            int gr = rowBase + row;
            v[i] = (gr < N_NODES) ? *(const float4*)(X + (size_t)gr * 256 + kt + aKq)
                                  : make_float4(0.f, 0.f, 0.f, 0.f);
        }
        __syncthreads();
        // convert fp32 -> fp16, store swizzled
        #pragma unroll
        for (int i = 0; i < 8; i++) {
            int row = aRow + i * 16;
            uint32_t p0 = pk_h2(__float2half(v[i].x), __float2half(v[i].y));
            uint32_t p1 = pk_h2(__float2half(v[i].z), __float2half(v[i].w));
            uint32_t off = SW128(row * 128 + aKq * 2);
            *(uint2*)(smem + G1_A + off) = make_uint2(p0, p1);
        }
        // B chunk: preconverted fp16 [n][k] slice, swizzled
        #pragma unroll
        for (int i = 0; i < 4; i++) {
            int gidx = tid + i * 256;               // 0..1023
            int n = gidx >> 3, q = gidx & 7;
            uint32_t off = SW128(n * 128 + q * 16);
            size_t gb = (size_t)n * 512 + (size_t)(kt + q * 8) * 2;
            *(uint4*)(smem + G1_B + off) = *(const uint4*)((const char*)g_W1h + gb);
        }
        __syncthreads();

        #pragma unroll
        for (int ks = 0; ks < 4; ks++) {
            int k0 = ks * 16;
            uint32_t aF[2][4];
            #pragma unroll
            for (int mt = 0; mt < 2; mt++) {
                int row = mw * 32 + mt * 16 + lr + ((lts & 1) << 3);
                int kk = k0 + ((lts >> 1) << 3);
                uint32_t off = SW128(row * 128 + kk * 2);
                ldsm_x4(sb + G1_A + off, aF[mt]);
            }
            #pragma unroll
            for (int q = 0; q < 2; q++) {
                int n = nw * 64 + (q * 4 + lts) * 8 + lr;
                uint32_t offLo = SW128(n * 128 + k0 * 2);
                uint32_t offHi = SW128(n * 128 + (k0 + 8) * 2);
                uint32_t t0[4], t1[4];
                ldsm_x4(sb + G1_B + offLo, t0);
                ldsm_x4(sb + G1_B + offHi, t1);
                #pragma unroll
                for (int j = 0; j < 4; j++) {
                    uint32_t bf[2] = { t0[j], t1[j] };
                    #pragma unroll
                    for (int mt = 0; mt < 2; mt++)
                        mma16816h(c[mt][q * 4 + j], aF[mt], bf);
                }
            }
        }
    }

    // epilogue: hs1 fp16, s02/s03 fp32
    #pragma unroll
    for (int mt = 0; mt < 2; mt++) {
        int r0 = rowBase + mw * 32 + mt * 16 + g;
        int r1 = r0 + 8;
        float dv0 = (r0 < N_NODES) ? g_dinv[r0] : 0.f;
        float dv1 = (r1 < N_NODES) ? g_dinv[r1] : 0.f;
        #pragma unroll
        for (int j = 0; j < 8; j++) {
            int col = nw * 64 + j * 8 + t4 * 2;
            float c0 = c[mt][j][0], c1 = c[mt][j][1];
            float c2 = c[mt][j][2], c3 = c[mt][j][3];
            if (r0 < N_NODES) {
                if (col < 64) {
                    *(__half2*)(g_hs1h + (size_t)r0 * 64 + col) = __floats2half2_rn(dv0 * c0, dv0 * c1);
                } else if (col < 96)  *(float2*)(g_s02 + (size_t)r0 * 32 + (col - 64)) = make_float2(c0, c1);
                else if (col < 112)   *(float2*)(g_s03 + (size_t)r0 * 16 + (col - 96)) = make_float2(c0, c1);
            }
            if (r1 < N_NODES) {
                if (col < 64) {
                    *(__half2*)(g_hs1h + (size_t)r1 * 64 + col) = __floats2half2_rn(dv1 * c2, dv1 * c3);
                } else if (col < 96)  *(float2*)(g_s02 + (size_t)r1 * 32 + (col - 64)) = make_float2(c2, c3);
                else if (col < 112)   *(float2*)(g_s03 + (size_t)r1 * 16 + (col - 96)) = make_float2(c2, c3);
            }
        }
    }
}

// ---------------- GEMM2 (mma.sync fp16): x1[100k,64] @ Wcat2[64,64] ----------------
#define G2_A 0
#define G2_B 16384
#define G2_TOTAL 24576

__global__ __launch_bounds__(256, 2) void k_gemm2_mma() {
    extern __shared__ __align__(1024) char smem[];
    uint32_t sb = smem_u32(smem);
    int tid = threadIdx.x, wid = tid >> 5, lane = tid & 31;
    int rowBase = blockIdx.x * 128;
    int mw = wid >> 1, nw = wid & 1;
    int g = lane >> 2, t4 = lane & 3;
    int lr = lane & 7, lts = lane >> 3;

    float c[2][4][4];
    #pragma unroll
    for (int a = 0; a < 2; a++)
        #pragma unroll
        for (int b = 0; b < 4; b++)
            #pragma unroll
            for (int d = 0; d < 4; d++) c[a][b][d] = 0.f;

    // A: x1 fp16, 128 rows x 64 k = 1024 16B-units
    #pragma unroll
    for (int i = 0; i < 4; i++) {
        int gidx = tid + i * 256;
        int row = gidx >> 3, q = gidx & 7;
        int gr = rowBase + row;
        uint32_t off = SW128(row * 128 + q * 16);
        if (gr < N_NODES) {
            *(uint4*)(smem + G2_A + off) = *(const uint4*)((const char*)g_x1h + (size_t)gr * 128 + (size_t)q * 16);
        } else {
            *(uint4*)(smem + G2_A + off) = make_uint4(0, 0, 0, 0);
        }
    }
    // B: 64 n x 64 k = 512 units
    #pragma unroll
    for (int i = 0; i < 2; i++) {
        int gidx = tid + i * 256;
        int n = gidx >> 3, q = gidx & 7;
        uint32_t off = SW128(n * 128 + q * 16);
        *(uint4*)(smem + G2_B + off) = *(const uint4*)((const char*)g_W2h + (size_t)n * 128 + (size_t)q * 16);
    }
    __syncthreads();

    #pragma unroll
    for (int ks = 0; ks < 4; ks++) {
        int k0 = ks * 16;
        uint32_t aF[2][4], bF[4][2];
        #pragma unroll
        for (int mt = 0; mt < 2; mt++) {
            int row = mw * 32 + mt * 16 + lr + ((lts & 1) << 3);
            int kk = k0 + ((lts >> 1) << 3);
            uint32_t off = SW128(row * 128 + kk * 2);
            ldsm_x4(sb + G2_A + off, aF[mt]);
        }
        {
            int n = nw * 32 + lts * 8 + lr;
            uint32_t offLo = SW128(n * 128 + k0 * 2);
            uint32_t offHi = SW128(n * 128 + (k0 + 8) * 2);
            uint32_t t0[4], t1[4];
            ldsm_x4(sb + G2_B + offLo, t0);
            ldsm_x4(sb + G2_B + offHi, t1);
            #pragma unroll
            for (int j = 0; j < 4; j++) { bF[j][0] = t0[j]; bF[j][1] = t1[j]; }
        }
        #pragma unroll
        for (int mt = 0; mt < 2; mt++)
            #pragma unroll
            for (int j = 0; j < 4; j++)
                mma16816h(c[mt][j], aF[mt], bF[j]);
    }

    #pragma unroll
    for (int mt = 0; mt < 2; mt++) {
        int r0 = rowBase + mw * 32 + mt * 16 + g;
        int r1 = r0 + 8;
        float dv0 = (r0 < N_NODES) ? g_dinv[r0] : 0.f;
        float dv1 = (r1 < N_NODES) ? g_dinv[r1] : 0.f;
        #pragma unroll
        for (int j = 0; j < 4; j++) {
            int col = nw * 32 + j * 8 + t4 * 2;
            float c0 = c[mt][j][0], c1 = c[mt][j][1];
            float c2 = c[mt][j][2], c3 = c[mt][j][3];
            if (r0 < N_NODES) {
                if (col < 32) {
                    *(__half2*)(g_hs2h + (size_t)r0 * 32 + col) = __floats2half2_rn(dv0 * c0, dv0 * c1);
                } else if (col < 48) *(float2*)(g_s13 + (size_t)r0 * 16 + (col - 32)) = make_float2(c0, c1);
            }
            if (r1 < N_NODES) {
                if (col < 32) {
                    *(__half2*)(g_hs2h + (size_t)r1 * 32 + col) = __floats2half2_rn(dv1 * c2, dv1 * c3);
                } else if (col < 48) *(float2*)(g_s13 + (size_t)r1 * 16 + (col - 32)) = make_float2(c2, c3);
            }
        }
    }
}

// ---------------- GEMM 3 (small): x2[100k,32] @ W3[32,16] ----------------
__global__ __launch_bounds__(256) void k_gemm3(const float* __restrict__ W3) {
    __shared__ float sW[32 * 16];
    int tid = threadIdx.x;
    sW[tid] = W3[tid];
    sW[tid + 256] = W3[tid + 256];
    __syncthreads();
    int gid = blockIdx.x * 256 + tid;
    int node = gid >> 4, cc = gid & 15;
    const __half2* xr = (const __half2*)(g_x2h + (size_t)node * 32);
    float acc = 0.f;
    #pragma unroll
    for (int k = 0; k < 16; k++) {
        float2 p = __half22float2(xr[k]);
        acc += p.x * sW[(2 * k) * 16 + cc] + p.y * sW[(2 * k + 1) * 16 + cc];
    }
    g_hs3h[gid] = __float2half(g_dinv[node] * acc);
}

// ---------------- warp-cooperative CSR aggregation (fp16 rows, uint4 lanes) ----------------
__global__ __launch_bounds__(256) void k_agg1(const float* __restrict__ b1) {
    int wid = threadIdx.x >> 5, lane = threadIdx.x & 31;
    int node = blockIdx.x * 8 + wid;
    int oc = lane >> 3, fl = lane & 7;
    const uint4* hs = (const uint4*)g_hs1h;
    int beg = g_rowptr[node], end = g_rowptr[node + 1];
    float f[8] = {0.f, 0.f, 0.f, 0.f, 0.f, 0.f, 0.f, 0.f};
    if (oc == 0) acc_u4(f, hs[(size_t)node * 8 + fl]);
    for (int e0 = beg; e0 < end; e0 += 32) {
        int n = end - e0; if (n > 32) n = 32;
        int idx = (lane < n) ? g_col[e0 + lane] : -1;
        int steps = (n + 3) >> 2;
        int t = 0;
        for (; t + 2 <= steps; t += 2) {
            int j0 = __shfl_sync(0xffffffffu, idx, 4 * t + oc);
            int j1 = __shfl_sync(0xffffffffu, idx, 4 * t + 4 + oc);
            if (j0 >= 0) acc_u4(f, hs[(size_t)j0 * 8 + fl]);
            if (j1 >= 0) acc_u4(f, hs[(size_t)j1 * 8 + fl]);
        }
        for (; t < steps; t++) {
            int j = __shfl_sync(0xffffffffu, idx, 4 * t + oc);
            if (j >= 0) acc_u4(f, hs[(size_t)j * 8 + fl]);
        }
    }
    #pragma unroll
    for (int i = 0; i < 8; i++) {
        f[i] += __shfl_xor_sync(0xffffffffu, f[i], 8);
        f[i] += __shfl_xor_sync(0xffffffffu, f[i], 16);
    }
    if (oc == 0) {
        float dv = g_dinv[node];
        float4 b0 = ((const float4*)b1)[2 * fl];
        float4 b4 = ((const float4*)b1)[2 * fl + 1];
        float o[8];
        o[0] = fmaxf(dv * f[0] + b0.x, 0.f); o[1] = fmaxf(dv * f[1] + b0.y, 0.f);
        o[2] = fmaxf(dv * f[2] + b0.z, 0.f); o[3] = fmaxf(dv * f[3] + b0.w, 0.f);
        o[4] = fmaxf(dv * f[4] + b4.x, 0.f); o[5] = fmaxf(dv * f[5] + b4.y, 0.f);
        o[6] = fmaxf(dv * f[6] + b4.z, 0.f); o[7] = fmaxf(dv * f[7] + b4.w, 0.f);
        uint4 hv;
        uint32_t* hp = (uint32_t*)&hv;
        #pragma unroll
        for (int q = 0; q < 4; q++) {
            __half2 p = __floats2half2_rn(o[2 * q], o[2 * q + 1]);
            hp[q] = *reinterpret_cast<uint32_t*>(&p);
        }
        ((uint4*)g_x1h)[(size_t)node * 8 + fl] = hv;
    }
}

__global__ __launch_bounds__(256) void k_agg2(const float* __restrict__ b2,
                                              const float* __restrict__ bs02) {
    int wid = threadIdx.x >> 5, lane = threadIdx.x & 31;
    int node = blockIdx.x * 8 + wid;
    int oc = lane >> 2, fl = lane & 3;
    const uint4* hs = (const uint4*)g_hs2h;
    int beg = g_rowptr[node], end = g_rowptr[node + 1];
    float f[8] = {0.f, 0.f, 0.f, 0.f, 0.f, 0.f, 0.f, 0.f};
    if (oc == 0) acc_u4(f, hs[(size_t)node * 4 + fl]);
    for (int e0 = beg; e0 < end; e0 += 32) {
        int n = end - e0; if (n > 32) n = 32;
        int idx = (lane < n) ? g_col[e0 + lane] : -1;
        int steps = (n + 7) >> 3;
        for (int t = 0; t < steps; t++) {
            int j = __shfl_sync(0xffffffffu, idx, 8 * t + oc);
            if (j >= 0) acc_u4(f, hs[(size_t)j * 4 + fl]);
        }
    }
    #pragma unroll
    for (int i = 0; i < 8; i++) {
        f[i] += __shfl_xor_sync(0xffffffffu, f[i], 4);
        f[i] += __shfl_xor_sync(0xffffffffu, f[i], 8);
        f[i] += __shfl_xor_sync(0xffffffffu, f[i], 16);
    }
    if (oc == 0) {
        float dv = g_dinv[node];
        float4 b0 = ((const float4*)b2)[2 * fl];
        float4 b4 = ((const float4*)b2)[2 * fl + 1];
        float4 sb0 = ((const float4*)bs02)[2 * fl];
        float4 sb4 = ((const float4*)bs02)[2 * fl + 1];
        float4 s0 = ((const float4*)g_s02)[(size_t)node * 8 + 2 * fl];
        float4 s4 = ((const float4*)g_s02)[(size_t)node * 8 + 2 * fl + 1];
        float o[8];
        o[0] = fmaxf(dv * f[0] + b0.x + s0.x + sb0.x, 0.f);
        o[1] = fmaxf(dv * f[1] + b0.y + s0.y + sb0.y, 0.f);
        o[2] = fmaxf(dv * f[2] + b0.z + s0.z + sb0.z, 0.f);
        o[3] = fmaxf(dv * f[3] + b0.w + s0.w + sb0.w, 0.f);
        o[4] = fmaxf(dv * f[4] + b4.x + s4.x + sb4.x, 0.f);
        o[5] = fmaxf(dv * f[5] + b4.y + s4.y + sb4.y, 0.f);
        o[6] = fmaxf(dv * f[6] + b4.z + s4.z + sb4.z, 0.f);
        o[7] = fmaxf(dv * f[7] + b4.w + s4.w + sb4.w, 0.f);
        uint4 hv;
        uint32_t* hp = (uint32_t*)&hv;
        #pragma unroll
        for (int q = 0; q < 4; q++) {
            __half2 p = __floats2half2_rn(o[2 * q], o[2 * q + 1]);
            hp[q] = *reinterpret_cast<uint32_t*>(&p);
        }
        ((uint4*)g_x2h)[(size_t)node * 4 + fl] = hv;
    }
}

__global__ __launch_bounds__(256) void k_agg3(const float* __restrict__ b3,
                                              const float* __restrict__ bs03,
                                              const float* __restrict__ bs13,
                                              const float* __restrict__ Wout,
                                              const float* __restrict__ bout,
                                              float* __restrict__ out) {
    int wid = threadIdx.x >> 5, lane = threadIdx.x & 31;
    int node = blockIdx.x * 8 + wid;
    int oc = lane >> 1, fl = lane & 1;
    const uint4* hs = (const uint4*)g_hs3h;
    int beg = g_rowptr[node], end = g_rowptr[node + 1];
    float f[8] = {0.f, 0.f, 0.f, 0.f, 0.f, 0.f, 0.f, 0.f};
    if (oc == 0) acc_u4(f, hs[(size_t)node * 2 + fl]);
    for (int e0 = beg; e0 < end; e0 += 32) {
        int n = end - e0; if (n > 32) n = 32;
        int idx = (lane < n) ? g_col[e0 + lane] : -1;
        int steps = (n + 15) >> 4;
        for (int t = 0; t < steps; t++) {
            int j = __shfl_sync(0xffffffffu, idx, 16 * t + oc);
            if (j >= 0) acc_u4(f, hs[(size_t)j * 2 + fl]);
        }
    }
    #pragma unroll
    for (int i = 0; i < 8; i++) {
        f[i] += __shfl_xor_sync(0xffffffffu, f[i], 2);
        f[i] += __shfl_xor_sync(0xffffffffu, f[i], 4);
        f[i] += __shfl_xor_sync(0xffffffffu, f[i], 8);
        f[i] += __shfl_xor_sync(0xffffffffu, f[i], 16);
    }
    float dv = g_dinv[node];
    float4 b0 = ((const float4*)b3)[2 * fl];
    float4 b4 = ((const float4*)b3)[2 * fl + 1];
    float4 q0 = ((const float4*)bs03)[2 * fl];
    float4 q4 = ((const float4*)bs03)[2 * fl + 1];
    float4 r0 = ((const float4*)bs13)[2 * fl];
    float4 r4 = ((const float4*)bs13)[2 * fl + 1];
    float4 s0 = ((const float4*)g_s03)[(size_t)node * 4 + 2 * fl];
    float4 s4 = ((const float4*)g_s03)[(size_t)node * 4 + 2 * fl + 1];
    float4 u0 = ((const float4*)g_s13)[(size_t)node * 4 + 2 * fl];
    float4 u4 = ((const float4*)g_s13)[(size_t)node * 4 + 2 * fl + 1];
    float4 w0 = ((const float4*)Wout)[2 * fl];
    float4 w4 = ((const float4*)Wout)[2 * fl + 1];
    float t0 = fmaxf(dv * f[0] + b0.x + s0.x + q0.x + u0.x + r0.x, 0.f);
    float t1 = fmaxf(dv * f[1] + b0.y + s0.y + q0.y + u0.y + r0.y, 0.f);
    float t2 = fmaxf(dv * f[2] + b0.z + s0.z + q0.z + u0.z + r0.z, 0.f);
    float t3 = fmaxf(dv * f[3] + b0.w + s0.w + q0.w + u0.w + r0.w, 0.f);
    float t4v = fmaxf(dv * f[4] + b4.x + s4.x + q4.x + u4.x + r4.x, 0.f);
    float t5 = fmaxf(dv * f[5] + b4.y + s4.y + q4.y + u4.y + r4.y, 0.f);
    float t6 = fmaxf(dv * f[6] + b4.z + s4.z + q4.z + u4.z + r4.z, 0.f);
    float t7 = fmaxf(dv * f[7] + b4.w + s4.w + q4.w + u4.w + r4.w, 0.f);
    float v = t0 * w0.x + t1 * w0.y + t2 * w0.z + t3 * w0.w
            + t4v * w4.x + t5 * w4.y + t6 * w4.z + t7 * w4.w;
    v += __shfl_xor_sync(0xffffffffu, v, 1);
    if (lane == 0) out[node] = 1.f / (1.f + __expf(-(v + bout[0])));
}

// ---------------- launch ----------------
extern "C" void kernel_launch(void* const* d_in, const int* in_sizes, int n_in,
                              void* d_out, int out_size) {
    const float* x    = (const float*)d_in[0];
    const int*   ei   = (const int*)d_in[1];
    const float* W1   = (const float*)d_in[2];
    const float* b1   = (const float*)d_in[3];
    const float* W2   = (const float*)d_in[4];
    const float* b2   = (const float*)d_in[5];
    const float* W3   = (const float*)d_in[6];
    const float* b3   = (const float*)d_in[7];
    const float* Ws02 = (const float*)d_in[8];
    const float* bs02 = (const float*)d_in[9];
    const float* Ws03 = (const float*)d_in[10];
    const float* bs03 = (const float*)d_in[11];
    const float* Ws13 = (const float*)d_in[12];
    const float* bs13 = (const float*)d_in[13];
    const float* Wout = (const float*)d_in[14];
    const float* bout = (const float*)d_in[15];
    float* out = (float*)d_out;

    const int* src = ei;
    const int* dst = ei + N_EDGES;

    cudaFuncSetAttribute(k_gemm1_mma, cudaFuncAttributeMaxDynamicSharedMemorySize, G1_TOTAL);
    cudaFuncSetAttribute(k_gemm2_mma, cudaFuncAttributeMaxDynamicSharedMemorySize, G2_TOTAL);

    void* p = nullptr;
    cudaGetSymbolAddress(&p, g_cnt);
    cudaMemsetAsync(p, 0, N_NODES * sizeof(int));
    cudaGetSymbolAddress(&p, g_bar);
    cudaMemsetAsync(p, 0, sizeof(int));

    k_csr<<<CSR_BLOCKS, 256>>>(src, dst);                           // 1
    k_pack1<<<(128 * 256 + 255) / 256, 256>>>(W1, Ws02, Ws03);      // 2
    k_gemm1_mma<<<(N_NODES + 127) / 128, 256, G1_TOTAL>>>(x);       // 3
    k_agg1<<<12500, 256>>>(b1);                                     // 4 (profiled)
    k_pack2<<<(64 * 64 + 255) / 256, 256>>>(W2, Ws13);              // 5
    k_gemm2_mma<<<(N_NODES + 127) / 128, 256, G2_TOTAL>>>();        // 6
    k_agg2<<<12500, 256>>>(b2, bs02);                               // 7
    k_gemm3<<<(N_NODES * 16 + 255) / 256, 256>>>(W3);               // 8
    k_agg3<<<12500, 256>>>(b3, bs03, bs13, Wout, bout, out);        // 9
}

// round 11
// speedup vs baseline: 1.3597x; 1.3597x over previous
#include <cuda_runtime.h>
#include <cuda_bf16.h>
#include <cuda_fp16.h>
#include <math.h>
#include <stdint.h>

#define N_NODES 100000
#define N_EDGES 3200000
#define CSR_BLOCKS 512

// ---------------- scratch (static __device__, no allocation) ----------------
__device__ int   g_bar;
__device__ int   g_bsum[CSR_BLOCKS];
__device__ int   g_cnt[N_NODES];
__device__ int   g_rowptr[N_NODES + 1];
__device__ int   g_cursor[N_NODES];
__device__ int   g_col[N_EDGES];
__device__ float g_dinv[N_NODES];
__device__ __align__(16) __half g_W1h[128 * 256];   // [n][k] concat W1|Ws02|Ws03 (transposed), fp16
__device__ __align__(16) __half g_W2h[64 * 64];     // [n][k] concat W2|Ws13 (transposed), fp16
__device__ __align__(16) __half g_hs1h[N_NODES * 64];  // fp16: dinv * (x @ W1)
__device__ __align__(16) float  g_s02[N_NODES * 32];   // x @ Ws02
__device__ __align__(16) float  g_s03[N_NODES * 16];   // x @ Ws03
__device__ __align__(16) __half g_x1h[N_NODES * 64];   // fp16 x1
__device__ __align__(16) __half g_hs2h[N_NODES * 32];  // fp16: dinv * (x1 @ W2)
__device__ __align__(16) float  g_s13[N_NODES * 16];   // x1 @ Ws13
__device__ __align__(16) __half g_x2h[N_NODES * 32];   // fp16 x2
__device__ __align__(16) __half g_hs3h[N_NODES * 16];  // fp16: dinv * (x2 @ W3)

// ---------------- helpers ----------------
__device__ __forceinline__ uint32_t smem_u32(const void* p) {
    uint32_t a;
    asm("{ .reg .u64 t; cvta.to.shared.u64 t, %1; cvt.u32.u64 %0, t; }" : "=r"(a) : "l"(p));
    return a;
}

#define SW128(o) ((uint32_t)(o) ^ ((((uint32_t)(o)) >> 3) & 0x70u))

__device__ __forceinline__ void ldsm_x4(uint32_t addr, uint32_t* r) {
    asm volatile("ldmatrix.sync.aligned.m8n8.x4.shared.b16 {%0,%1,%2,%3}, [%4];"
                 : "=r"(r[0]), "=r"(r[1]), "=r"(r[2]), "=r"(r[3]) : "r"(addr));
}

// fp16 x fp16 -> fp32 accumulate
__device__ __forceinline__ void mma16816h(float* c, const uint32_t* a, const uint32_t* b) {
    asm volatile(
        "mma.sync.aligned.m16n8k16.row.col.f32.f16.f16.f32 "
        "{%0,%1,%2,%3}, {%4,%5,%6,%7}, {%8,%9}, {%0,%1,%2,%3};"
        : "+f"(c[0]), "+f"(c[1]), "+f"(c[2]), "+f"(c[3])
        : "r"(a[0]), "r"(a[1]), "r"(a[2]), "r"(a[3]), "r"(b[0]), "r"(b[1]));
}

__device__ __forceinline__ uint32_t pk_h2(__half a, __half b) {
    __half2 t;
    t.x = a; t.y = b;
    return *reinterpret_cast<uint32_t*>(&t);
}

__device__ __forceinline__ void acc_u4(float* f, uint4 v) {
    float2 p;
    p = __half22float2(*reinterpret_cast<__half2*>(&v.x)); f[0] += p.x; f[1] += p.y;
    p = __half22float2(*reinterpret_cast<__half2*>(&v.y)); f[2] += p.x; f[3] += p.y;
    p = __half22float2(*reinterpret_cast<__half2*>(&v.z)); f[4] += p.x; f[5] += p.y;
    p = __half22float2(*reinterpret_cast<__half2*>(&v.w)); f[6] += p.x; f[7] += p.y;
}

// ---------------- fused CSR build (persistent grid, atomic barriers) ----------------
// R9-proven barrier form (atomicAdd poll + threadfence) — the R10 ld.acquire
// variant coincided with a +77us regression and is reverted.
__device__ __forceinline__ void grid_bar(int target) {
    __syncthreads();
    if (threadIdx.x == 0) {
        __threadfence();
        atomicAdd(&g_bar, 1);
        while (atomicAdd(&g_bar, 0) < target) __nanosleep(64);
        __threadfence();
    }
    __syncthreads();
}

__global__ __launch_bounds__(256, 4) void k_csr(const int* __restrict__ src,
                                               const int* __restrict__ dst) {
    const int B = CSR_BLOCKS;
    int tid = threadIdx.x, b = blockIdx.x;
    int gthreads = B * 256;
    int gt = b * 256 + tid;
    __shared__ int sm[256];

    // P1: degree count
    for (int e = gt; e < N_EDGES; e += gthreads)
        atomicAdd(&g_cnt[dst[e]], 1);
    grid_bar(B);

    // P2a: per-block partial sum over node chunk
    const int CH = (N_NODES + B - 1) / B;          // 196
    int nb = b * CH;
    int ne = nb + CH; if (ne > N_NODES) ne = N_NODES;
    int s = 0;
    for (int i = nb + tid; i < ne; i += 256) s += g_cnt[i];
    sm[tid] = s;
    __syncthreads();
    for (int off = 128; off > 0; off >>= 1) {
        if (tid < off) sm[tid] += sm[tid + off];
        __syncthreads();
    }
    if (tid == 0) g_bsum[b] = sm[0];
    grid_bar(2 * B);

    // P2b: block 0 exclusive-scans the 512 partials
    if (b == 0) {
        int i0 = 2 * tid, i1 = 2 * tid + 1;
        int v0 = (i0 < B) ? g_bsum[i0] : 0;
        int v1 = (i1 < B) ? g_bsum[i1] : 0;
        int tsum = v0 + v1;
        __syncthreads();
        sm[tid] = tsum;
        __syncthreads();
        for (int off = 1; off < 256; off <<= 1) {
            int x = (tid >= off) ? sm[tid - off] : 0;
            __syncthreads();
            sm[tid] += x;
            __syncthreads();
        }
        int run = (tid == 0) ? 0 : sm[tid - 1];
        if (i0 < B) g_bsum[i0] = run;
        run += v0;
        if (i1 < B) g_bsum[i1] = run;
        if (tid == 255) g_rowptr[N_NODES] = sm[255];
    }
    grid_bar(3 * B);

    // P2c: write rowptr/cursor/dinv for this block's chunk (CH=196 <= 256)
    {
        int cnt_n = ne - nb;
        int myc = 0;
        if (tid < cnt_n) myc = g_cnt[nb + tid];
        __syncthreads();
        sm[tid] = myc;
        __syncthreads();
        for (int off = 1; off < 256; off <<= 1) {
            int x = (tid >= off) ? sm[tid - off] : 0;
            __syncthreads();
            sm[tid] += x;
            __syncthreads();
        }
        if (tid < cnt_n) {
            int run = g_bsum[b] + ((tid == 0) ? 0 : sm[tid - 1]);
            g_rowptr[nb + tid] = run;
            g_cursor[nb + tid] = run;
            g_dinv[nb + tid] = rsqrtf((float)myc + 1.0f);
        }
    }
    grid_bar(4 * B);

    // P3: fill (cursor clamp protects against profiler kernel-replay state corruption)
    for (int e = gt; e < N_EDGES; e += gthreads) {
        int d = dst[e];
        int p = atomicAdd(&g_cursor[d], 1);
        if (p < N_EDGES) g_col[p] = src[e];
    }
}

// ---------------- weight packing ([n][k] transposed, fp16) ----------------
__global__ void k_pack1(const float* __restrict__ W1, const float* __restrict__ Ws02,
                        const float* __restrict__ Ws03) {
    int i = blockIdx.x * 256 + threadIdx.x;
    if (i >= 128 * 256) return;
    int n = i >> 8, k = i & 255;
    float v = 0.f;
    if (n < 64)       v = W1[k * 64 + n];
    else if (n < 96)  v = Ws02[k * 32 + (n - 64)];
    else if (n < 112) v = Ws03[k * 16 + (n - 96)];
    g_W1h[i] = __float2half(v);
}

__global__ void k_pack2(const float* __restrict__ W2, const float* __restrict__ Ws13) {
    int i = blockIdx.x * 256 + threadIdx.x;
    if (i >= 64 * 64) return;
    int n = i >> 6, k = i & 63;
    float v = 0.f;
    if (n < 32)      v = W2[k * 32 + n];
    else if (n < 48) v = Ws13[k * 16 + (n - 32)];
    g_W2h[i] = __float2half(v);
}

// ---------------- GEMM1 (mma.sync fp16 single-plane): x[100k,256] @ Wcat1[256,128] ----------------
// CTA: 128 rows x 128 cols, K in 4 chunks of 64. 8 warps as 4(m) x 2(n); warp tile 32x64.
#define G1_A 0
#define G1_B 16384
#define G1_TOTAL 32768

__global__ __launch_bounds__(256, 2) void k_gemm1_mma(const float* __restrict__ X) {
    extern __shared__ __align__(1024) char smem[];
    uint32_t sb = smem_u32(smem);
    int tid = threadIdx.x, wid = tid >> 5, lane = tid & 31;
    int rowBase = blockIdx.x * 128;
    int mw = wid >> 1, nw = wid & 1;          // 4 m-warps x 2 n-warps
    int g = lane >> 2, t4 = lane & 3;

    float c[2][8][4];
    #pragma unroll
    for (int a = 0; a < 2; a++)
        #pragma unroll
        for (int b = 0; b < 8; b++)
            #pragma unroll
            for (int d = 0; d < 4; d++) c[a][b][d] = 0.f;

    int lr = lane & 7, lts = lane >> 3;
    int aRow = tid >> 4, aKq = (tid & 15) * 4;

    for (int ch = 0; ch < 4; ch++) {
        int kt = ch * 64;
        // prefetch A chunk (overlaps previous MMA phase)
        float4 v[8];
        #pragma unroll
        for (int i = 0; i < 8; i++) {
            int row = aRow + i * 16;
            int gr = rowBase + row;
            v[i] = (gr < N_NODES) ? *(const float4*)(X + (size_t)gr * 256 + kt + aKq)
                                  : make_float4(0.f, 0.f, 0.f, 0.f);
        }
        __syncthreads();
        // convert fp32 -> fp16, store swizzled
        #pragma unroll
        for (int i = 0; i < 8; i++) {
            int row = aRow + i * 16;
            uint32_t p0 = pk_h2(__float2half(v[i].x), __float2half(v[i].y));
            uint32_t p1 = pk_h2(__float2half(v[i].z), __float2half(v[i].w));
            uint32_t off = SW128(row * 128 + aKq * 2);
            *(uint2*)(smem + G1_A + off) = make_uint2(p0, p1);
        }
        // B chunk: preconverted fp16 [n][k] slice, swizzled
        #pragma unroll
        for (int i = 0; i < 4; i++) {
            int gidx = tid + i * 256;               // 0..1023
            int n = gidx >> 3, q = gidx & 7;
            uint32_t off = SW128(n * 128 + q * 16);
            size_t gb = (size_t)n * 512 + (size_t)(kt + q * 8) * 2;
            *(uint4*)(smem + G1_B + off) = *(const uint4*)((const char*)g_W1h + gb);
        }
        __syncthreads();

        #pragma unroll
        for (int ks = 0; ks < 4; ks++) {
            int k0 = ks * 16;
            uint32_t aF[2][4];
            #pragma unroll
            for (int mt = 0; mt < 2; mt++) {
                int row = mw * 32 + mt * 16 + lr + ((lts & 1) << 3);
                int kk = k0 + ((lts >> 1) << 3);
                uint32_t off = SW128(row * 128 + kk * 2);
                ldsm_x4(sb + G1_A + off, aF[mt]);
            }
            #pragma unroll
            for (int q = 0; q < 2; q++) {
                int n = nw * 64 + (q * 4 + lts) * 8 + lr;
                uint32_t offLo = SW128(n * 128 + k0 * 2);
                uint32_t offHi = SW128(n * 128 + (k0 + 8) * 2);
                uint32_t t0[4], t1[4];
                ldsm_x4(sb + G1_B + offLo, t0);
                ldsm_x4(sb + G1_B + offHi, t1);
                #pragma unroll
                for (int j = 0; j < 4; j++) {
                    uint32_t bf[2] = { t0[j], t1[j] };
                    #pragma unroll
                    for (int mt = 0; mt < 2; mt++)
                        mma16816h(c[mt][q * 4 + j], aF[mt], bf);
                }
            }
        }
    }

    // epilogue: hs1 fp16, s02/s03 fp32
    #pragma unroll
    for (int mt = 0; mt < 2; mt++) {
        int r0 = rowBase + mw * 32 + mt * 16 + g;
        int r1 = r0 + 8;
        float dv0 = (r0 < N_NODES) ? g_dinv[r0] : 0.f;
        float dv1 = (r1 < N_NODES) ? g_dinv[r1] : 0.f;
        #pragma unroll
        for (int j = 0; j < 8; j++) {
            int col = nw * 64 + j * 8 + t4 * 2;
            float c0 = c[mt][j][0], c1 = c[mt][j][1];
            float c2 = c[mt][j][2], c3 = c[mt][j][3];
            if (r0 < N_NODES) {
                if (col < 64) {
                    *(__half2*)(g_hs1h + (size_t)r0 * 64 + col) = __floats2half2_rn(dv0 * c0, dv0 * c1);
                } else if (col < 96)  *(float2*)(g_s02 + (size_t)r0 * 32 + (col - 64)) = make_float2(c0, c1);
                else if (col < 112)   *(float2*)(g_s03 + (size_t)r0 * 16 + (col - 96)) = make_float2(c0, c1);
            }
            if (r1 < N_NODES) {
                if (col < 64) {
                    *(__half2*)(g_hs1h + (size_t)r1 * 64 + col) = __floats2half2_rn(dv1 * c2, dv1 * c3);
                } else if (col < 96)  *(float2*)(g_s02 + (size_t)r1 * 32 + (col - 64)) = make_float2(c2, c3);
                else if (col < 112)   *(float2*)(g_s03 + (size_t)r1 * 16 + (col - 96)) = make_float2(c2, c3);
            }
        }
    }
}

// ---------------- GEMM2 (mma.sync fp16): x1[100k,64] @ Wcat2[64,64] ----------------
#define G2_A 0
#define G2_B 16384
#define G2_TOTAL 24576

__global__ __launch_bounds__(256, 2) void k_gemm2_mma() {
    extern __shared__ __align__(1024) char smem[];
    uint32_t sb = smem_u32(smem);
    int tid = threadIdx.x, wid = tid >> 5, lane = tid & 31;
    int rowBase = blockIdx.x * 128;
    int mw = wid >> 1, nw = wid & 1;
    int g = lane >> 2, t4 = lane & 3;
    int lr = lane & 7, lts = lane >> 3;

    float c[2][4][4];
    #pragma unroll
    for (int a = 0; a < 2; a++)
        #pragma unroll
        for (int b = 0; b < 4; b++)
            #pragma unroll
            for (int d = 0; d < 4; d++) c[a][b][d] = 0.f;

    // A: x1 fp16, 128 rows x 64 k = 1024 16B-units
    #pragma unroll
    for (int i = 0; i < 4; i++) {
        int gidx = tid + i * 256;
        int row = gidx >> 3, q = gidx & 7;
        int gr = rowBase + row;
        uint32_t off = SW128(row * 128 + q * 16);
        if (gr < N_NODES) {
            *(uint4*)(smem + G2_A + off) = *(const uint4*)((const char*)g_x1h + (size_t)gr * 128 + (size_t)q * 16);
        } else {
            *(uint4*)(smem + G2_A + off) = make_uint4(0, 0, 0, 0);
        }
    }
    // B: 64 n x 64 k = 512 units
    #pragma unroll
    for (int i = 0; i < 2; i++) {
        int gidx = tid + i * 256;
        int n = gidx >> 3, q = gidx & 7;
        uint32_t off = SW128(n * 128 + q * 16);
        *(uint4*)(smem + G2_B + off) = *(const uint4*)((const char*)g_W2h + (size_t)n * 128 + (size_t)q * 16);
    }
    __syncthreads();

    #pragma unroll
    for (int ks = 0; ks < 4; ks++) {
        int k0 = ks * 16;
        uint32_t aF[2][4], bF[4][2];
        #pragma unroll
        for (int mt = 0; mt < 2; mt++) {
            int row = mw * 32 + mt * 16 + lr + ((lts & 1) << 3);
            int kk = k0 + ((lts >> 1) << 3);
            uint32_t off = SW128(row * 128 + kk * 2);
            ldsm_x4(sb + G2_A + off, aF[mt]);
        }
        {
            int n = nw * 32 + lts * 8 + lr;
            uint32_t offLo = SW128(n * 128 + k0 * 2);
            uint32_t offHi = SW128(n * 128 + (k0 + 8) * 2);
            uint32_t t0[4], t1[4];
            ldsm_x4(sb + G2_B + offLo, t0);
            ldsm_x4(sb + G2_B + offHi, t1);
            #pragma unroll
            for (int j = 0; j < 4; j++) { bF[j][0] = t0[j]; bF[j][1] = t1[j]; }
        }
        #pragma unroll
        for (int mt = 0; mt < 2; mt++)
            #pragma unroll
            for (int j = 0; j < 4; j++)
                mma16816h(c[mt][j], aF[mt], bF[j]);
    }

    #pragma unroll
    for (int mt = 0; mt < 2; mt++) {
        int r0 = rowBase + mw * 32 + mt * 16 + g;
        int r1 = r0 + 8;
        float dv0 = (r0 < N_NODES) ? g_dinv[r0] : 0.f;
        float dv1 = (r1 < N_NODES) ? g_dinv[r1] : 0.f;
        #pragma unroll
        for (int j = 0; j < 4; j++) {
            int col = nw * 32 + j * 8 + t4 * 2;
            float c0 = c[mt][j][0], c1 = c[mt][j][1];
            float c2 = c[mt][j][2], c3 = c[mt][j][3];
            if (r0 < N_NODES) {
                if (col < 32) {
                    *(__half2*)(g_hs2h + (size_t)r0 * 32 + col) = __floats2half2_rn(dv0 * c0, dv0 * c1);
                } else if (col < 48) *(float2*)(g_s13 + (size_t)r0 * 16 + (col - 32)) = make_float2(c0, c1);
            }
            if (r1 < N_NODES) {
                if (col < 32) {
                    *(__half2*)(g_hs2h + (size_t)r1 * 32 + col) = __floats2half2_rn(dv1 * c2, dv1 * c3);
                } else if (col < 48) *(float2*)(g_s13 + (size_t)r1 * 16 + (col - 32)) = make_float2(c2, c3);
            }
        }
    }
}

// ---------------- GEMM 3 (small): x2[100k,32] @ W3[32,16] ----------------
__global__ __launch_bounds__(256) void k_gemm3(const float* __restrict__ W3) {
    __shared__ float sW[32 * 16];
    int tid = threadIdx.x;
    sW[tid] = W3[tid];
    sW[tid + 256] = W3[tid + 256];
    __syncthreads();
    int gid = blockIdx.x * 256 + tid;
    int node = gid >> 4, cc = gid & 15;
    const __half2* xr = (const __half2*)(g_x2h + (size_t)node * 32);
    float acc = 0.f;
    #pragma unroll
    for (int k = 0; k < 16; k++) {
        float2 p = __half22float2(xr[k]);
        acc += p.x * sW[(2 * k) * 16 + cc] + p.y * sW[(2 * k + 1) * 16 + cc];
    }
    g_hs3h[gid] = __float2half(g_dinv[node] * acc);
}

// ---------------- warp-cooperative CSR aggregation (fp16 rows, uint4 lanes) ----------------
__global__ __launch_bounds__(256) void k_agg1(const float* __restrict__ b1) {
    int wid = threadIdx.x >> 5, lane = threadIdx.x & 31;
    int node = blockIdx.x * 8 + wid;
    int oc = lane >> 3, fl = lane & 7;
    const uint4* hs = (const uint4*)g_hs1h;
    int beg = g_rowptr[node], end = g_rowptr[node + 1];
    float f[8] = {0.f, 0.f, 0.f, 0.f, 0.f, 0.f, 0.f, 0.f};
    if (oc == 0) acc_u4(f, hs[(size_t)node * 8 + fl]);
    for (int e0 = beg; e0 < end; e0 += 32) {
        int n = end - e0; if (n > 32) n = 32;
        int idx = (lane < n) ? g_col[e0 + lane] : -1;
        int steps = (n + 3) >> 2;
        int t = 0;
        for (; t + 2 <= steps; t += 2) {
            int j0 = __shfl_sync(0xffffffffu, idx, 4 * t + oc);
            int j1 = __shfl_sync(0xffffffffu, idx, 4 * t + 4 + oc);
            if (j0 >= 0) acc_u4(f, hs[(size_t)j0 * 8 + fl]);
            if (j1 >= 0) acc_u4(f, hs[(size_t)j1 * 8 + fl]);
        }
        for (; t < steps; t++) {
            int j = __shfl_sync(0xffffffffu, idx, 4 * t + oc);
            if (j >= 0) acc_u4(f, hs[(size_t)j * 8 + fl]);
        }
    }
    #pragma unroll
    for (int i = 0; i < 8; i++) {
        f[i] += __shfl_xor_sync(0xffffffffu, f[i], 8);
        f[i] += __shfl_xor_sync(0xffffffffu, f[i], 16);
    }
    if (oc == 0) {
        float dv = g_dinv[node];
        float4 b0 = ((const float4*)b1)[2 * fl];
        float4 b4 = ((const float4*)b1)[2 * fl + 1];
        float o[8];
        o[0] = fmaxf(dv * f[0] + b0.x, 0.f); o[1] = fmaxf(dv * f[1] + b0.y, 0.f);
        o[2] = fmaxf(dv * f[2] + b0.z, 0.f); o[3] = fmaxf(dv * f[3] + b0.w, 0.f);
        o[4] = fmaxf(dv * f[4] + b4.x, 0.f); o[5] = fmaxf(dv * f[5] + b4.y, 0.f);
        o[6] = fmaxf(dv * f[6] + b4.z, 0.f); o[7] = fmaxf(dv * f[7] + b4.w, 0.f);
        uint4 hv;
        uint32_t* hp = (uint32_t*)&hv;
        #pragma unroll
        for (int q = 0; q < 4; q++) {
            __half2 p = __floats2half2_rn(o[2 * q], o[2 * q + 1]);
            hp[q] = *reinterpret_cast<uint32_t*>(&p);
        }
        ((uint4*)g_x1h)[(size_t)node * 8 + fl] = hv;
    }
}

__global__ __launch_bounds__(256) void k_agg2(const float* __restrict__ b2,
                                              const float* __restrict__ bs02) {
    int wid = threadIdx.x >> 5, lane = threadIdx.x & 31;
    int node = blockIdx.x * 8 + wid;
    int oc = lane >> 2, fl = lane & 3;
    const uint4* hs = (const uint4*)g_hs2h;
    int beg = g_rowptr[node], end = g_rowptr[node + 1];
    float f[8] = {0.f, 0.f, 0.f, 0.f, 0.f, 0.f, 0.f, 0.f};
    if (oc == 0) acc_u4(f, hs[(size_t)node * 4 + fl]);
    for (int e0 = beg; e0 < end; e0 += 32) {
        int n = end - e0; if (n > 32) n = 32;
        int idx = (lane < n) ? g_col[e0 + lane] : -1;
        int steps = (n + 7) >> 3;
        for (int t = 0; t < steps; t++) {
            int j = __shfl_sync(0xffffffffu, idx, 8 * t + oc);
            if (j >= 0) acc_u4(f, hs[(size_t)j * 4 + fl]);
        }
    }
    #pragma unroll
    for (int i = 0; i < 8; i++) {
        f[i] += __shfl_xor_sync(0xffffffffu, f[i], 4);
        f[i] += __shfl_xor_sync(0xffffffffu, f[i], 8);
        f[i] += __shfl_xor_sync(0xffffffffu, f[i], 16);
    }
    if (oc == 0) {
        float dv = g_dinv[node];
        float4 b0 = ((const float4*)b2)[2 * fl];
        float4 b4 = ((const float4*)b2)[2 * fl + 1];
        float4 sb0 = ((const float4*)bs02)[2 * fl];
        float4 sb4 = ((const float4*)bs02)[2 * fl + 1];
        float4 s0 = ((const float4*)g_s02)[(size_t)node * 8 + 2 * fl];
        float4 s4 = ((const float4*)g_s02)[(size_t)node * 8 + 2 * fl + 1];
        float o[8];
        o[0] = fmaxf(dv * f[0] + b0.x + s0.x + sb0.x, 0.f);
        o[1] = fmaxf(dv * f[1] + b0.y + s0.y + sb0.y, 0.f);
        o[2] = fmaxf(dv * f[2] + b0.z + s0.z + sb0.z, 0.f);
        o[3] = fmaxf(dv * f[3] + b0.w + s0.w + sb0.w, 0.f);
        o[4] = fmaxf(dv * f[4] + b4.x + s4.x + sb4.x, 0.f);
        o[5] = fmaxf(dv * f[5] + b4.y + s4.y + sb4.y, 0.f);
        o[6] = fmaxf(dv * f[6] + b4.z + s4.z + sb4.z, 0.f);
        o[7] = fmaxf(dv * f[7] + b4.w + s4.w + sb4.w, 0.f);
        uint4 hv;
        uint32_t* hp = (uint32_t*)&hv;
        #pragma unroll
        for (int q = 0; q < 4; q++) {
            __half2 p = __floats2half2_rn(o[2 * q], o[2 * q + 1]);
            hp[q] = *reinterpret_cast<uint32_t*>(&p);
        }
        ((uint4*)g_x2h)[(size_t)node * 4 + fl] = hv;
    }
}

__global__ __launch_bounds__(256) void k_agg3(const float* __restrict__ b3,
                                              const float* __restrict__ bs03,
                                              const float* __restrict__ bs13,
                                              const float* __restrict__ Wout,
                                              const float* __restrict__ bout,
                                              float* __restrict__ out) {
    int wid = threadIdx.x >> 5, lane = threadIdx.x & 31;
    int node = blockIdx.x * 8 + wid;
    int oc = lane >> 1, fl = lane & 1;
    const uint4* hs = (const uint4*)g_hs3h;
    int beg = g_rowptr[node], end = g_rowptr[node + 1];
    float f[8] = {0.f, 0.f, 0.f, 0.f, 0.f, 0.f, 0.f, 0.f};
    if (oc == 0) acc_u4(f, hs[(size_t)node * 2 + fl]);
    for (int e0 = beg; e0 < end; e0 += 32) {
        int n = end - e0; if (n > 32) n = 32;
        int idx = (lane < n) ? g_col[e0 + lane] : -1;
        int steps = (n + 15) >> 4;
        for (int t = 0; t < steps; t++) {
            int j = __shfl_sync(0xffffffffu, idx, 16 * t + oc);
            if (j >= 0) acc_u4(f, hs[(size_t)j * 2 + fl]);
        }
    }
    #pragma unroll
    for (int i = 0; i < 8; i++) {
        f[i] += __shfl_xor_sync(0xffffffffu, f[i], 2);
        f[i] += __shfl_xor_sync(0xffffffffu, f[i], 4);
        f[i] += __shfl_xor_sync(0xffffffffu, f[i], 8);
        f[i] += __shfl_xor_sync(0xffffffffu, f[i], 16);
    }
    float dv = g_dinv[node];
    float4 b0 = ((const float4*)b3)[2 * fl];
    float4 b4 = ((const float4*)b3)[2 * fl + 1];
    float4 q0 = ((const float4*)bs03)[2 * fl];
    float4 q4 = ((const float4*)bs03)[2 * fl + 1];
    float4 r0 = ((const float4*)bs13)[2 * fl];
    float4 r4 = ((const float4*)bs13)[2 * fl + 1];
    float4 s0 = ((const float4*)g_s03)[(size_t)node * 4 + 2 * fl];
    float4 s4 = ((const float4*)g_s03)[(size_t)node * 4 + 2 * fl + 1];
    float4 u0 = ((const float4*)g_s13)[(size_t)node * 4 + 2 * fl];
    float4 u4 = ((const float4*)g_s13)[(size_t)node * 4 + 2 * fl + 1];
    float4 w0 = ((const float4*)Wout)[2 * fl];
    float4 w4 = ((const float4*)Wout)[2 * fl + 1];
    float t0 = fmaxf(dv * f[0] + b0.x + s0.x + q0.x + u0.x + r0.x, 0.f);
    float t1 = fmaxf(dv * f[1] + b0.y + s0.y + q0.y + u0.y + r0.y, 0.f);
    float t2 = fmaxf(dv * f[2] + b0.z + s0.z + q0.z + u0.z + r0.z, 0.f);
    float t3 = fmaxf(dv * f[3] + b0.w + s0.w + q0.w + u0.w + r0.w, 0.f);
    float t4v = fmaxf(dv * f[4] + b4.x + s4.x + q4.x + u4.x + r4.x, 0.f);
    float t5 = fmaxf(dv * f[5] + b4.y + s4.y + q4.y + u4.y + r4.y, 0.f);
    float t6 = fmaxf(dv * f[6] + b4.z + s4.z + q4.z + u4.z + r4.z, 0.f);
    float t7 = fmaxf(dv * f[7] + b4.w + s4.w + q4.w + u4.w + r4.w, 0.f);
    float v = t0 * w0.x + t1 * w0.y + t2 * w0.z + t3 * w0.w
            + t4v * w4.x + t5 * w4.y + t6 * w4.z + t7 * w4.w;
    v += __shfl_xor_sync(0xffffffffu, v, 1);
    if (lane == 0) out[node] = 1.f / (1.f + __expf(-(v + bout[0])));
}

// ---------------- launch ----------------
extern "C" void kernel_launch(void* const* d_in, const int* in_sizes, int n_in,
                              void* d_out, int out_size) {
    const float* x    = (const float*)d_in[0];
    const int*   ei   = (const int*)d_in[1];
    const float* W1   = (const float*)d_in[2];
    const float* b1   = (const float*)d_in[3];
    const float* W2   = (const float*)d_in[4];
    const float* b2   = (const float*)d_in[5];
    const float* W3   = (const float*)d_in[6];
    const float* b3   = (const float*)d_in[7];
    const float* Ws02 = (const float*)d_in[8];
    const float* bs02 = (const float*)d_in[9];
    const float* Ws03 = (const float*)d_in[10];
    const float* bs03 = (const float*)d_in[11];
    const float* Ws13 = (const float*)d_in[12];
    const float* bs13 = (const float*)d_in[13];
    const float* Wout = (const float*)d_in[14];
    const float* bout = (const float*)d_in[15];
    float* out = (float*)d_out;

    const int* src = ei;
    const int* dst = ei + N_EDGES;

    cudaFuncSetAttribute(k_gemm1_mma, cudaFuncAttributeMaxDynamicSharedMemorySize, G1_TOTAL);
    cudaFuncSetAttribute(k_gemm2_mma, cudaFuncAttributeMaxDynamicSharedMemorySize, G2_TOTAL);

    void* p = nullptr;
    cudaGetSymbolAddress(&p, g_cnt);
    cudaMemsetAsync(p, 0, N_NODES * sizeof(int));
    cudaGetSymbolAddress(&p, g_bar);
    cudaMemsetAsync(p, 0, sizeof(int));

    k_csr<<<CSR_BLOCKS, 256>>>(src, dst);                           // 1
    k_pack1<<<(128 * 256 + 255) / 256, 256>>>(W1, Ws02, Ws03);      // 2
    k_pack2<<<(64 * 64 + 255) / 256, 256>>>(W2, Ws13);              // 3
    k_gemm1_mma<<<(N_NODES + 127) / 128, 256, G1_TOTAL>>>(x);       // 4 (profiled)
    k_agg1<<<12500, 256>>>(b1);                                     // 5
    k_gemm2_mma<<<(N_NODES + 127) / 128, 256, G2_TOTAL>>>();        // 6
    k_agg2<<<12500, 256>>>(b2, bs02);                               // 7
    k_gemm3<<<(N_NODES * 16 + 255) / 256, 256>>>(W3);               // 8
    k_agg3<<<12500, 256>>>(b3, bs03, bs13, Wout, bout, out);        // 9
}

// round 12
// speedup vs baseline: 1.3779x; 1.0134x over previous
#include <cuda_runtime.h>
#include <cuda_bf16.h>
#include <cuda_fp16.h>
#include <math.h>
#include <stdint.h>

#define N_NODES 100000
#define N_EDGES 3200000
#define CSR_BLOCKS 512
#define G1_BLOCKS 782          // ceil(100000/128)
#define FILL_BLOCKS 1563

// ---------------- scratch (static __device__, no allocation) ----------------
__device__ int   g_bar;
__device__ int   g_bsum[CSR_BLOCKS];
__device__ int   g_cnt[N_NODES];
__device__ int   g_rowptr[N_NODES + 1];
__device__ int   g_cursor[N_NODES];
__device__ int   g_col[N_EDGES];
__device__ float g_dinv[N_NODES];
__device__ __align__(16) __half g_W1h[128 * 256];   // [n][k] concat W1|Ws02|Ws03 (transposed), fp16
__device__ __align__(16) __half g_W2h[64 * 64];     // [n][k] concat W2|Ws13 (transposed), fp16
__device__ __align__(16) __half g_hs1h[N_NODES * 64];  // fp16: dinv * (x @ W1)
__device__ __align__(16) float  g_s02[N_NODES * 32];   // x @ Ws02
__device__ __align__(16) float  g_s03[N_NODES * 16];   // x @ Ws03
__device__ __align__(16) __half g_x1h[N_NODES * 64];   // fp16 x1
__device__ __align__(16) __half g_hs2h[N_NODES * 32];  // fp16: dinv * (x1 @ W2)
__device__ __align__(16) float  g_s13[N_NODES * 16];   // x1 @ Ws13
__device__ __align__(16) __half g_x2h[N_NODES * 32];   // fp16 x2
__device__ __align__(16) __half g_hs3h[N_NODES * 16];  // fp16: dinv * (x2 @ W3)

// ---------------- helpers ----------------
__device__ __forceinline__ uint32_t smem_u32(const void* p) {
    uint32_t a;
    asm("{ .reg .u64 t; cvta.to.shared.u64 t, %1; cvt.u32.u64 %0, t; }" : "=r"(a) : "l"(p));
    return a;
}

#define SW128(o) ((uint32_t)(o) ^ ((((uint32_t)(o)) >> 3) & 0x70u))

__device__ __forceinline__ void ldsm_x4(uint32_t addr, uint32_t* r) {
    asm volatile("ldmatrix.sync.aligned.m8n8.x4.shared.b16 {%0,%1,%2,%3}, [%4];"
                 : "=r"(r[0]), "=r"(r[1]), "=r"(r[2]), "=r"(r[3]) : "r"(addr));
}

// fp16 x fp16 -> fp32 accumulate
__device__ __forceinline__ void mma16816h(float* c, const uint32_t* a, const uint32_t* b) {
    asm volatile(
        "mma.sync.aligned.m16n8k16.row.col.f32.f16.f16.f32 "
        "{%0,%1,%2,%3}, {%4,%5,%6,%7}, {%8,%9}, {%0,%1,%2,%3};"
        : "+f"(c[0]), "+f"(c[1]), "+f"(c[2]), "+f"(c[3])
        : "r"(a[0]), "r"(a[1]), "r"(a[2]), "r"(a[3]), "r"(b[0]), "r"(b[1]));
}

__device__ __forceinline__ uint32_t pk_h2(__half a, __half b) {
    __half2 t;
    t.x = a; t.y = b;
    return *reinterpret_cast<uint32_t*>(&t);
}

__device__ __forceinline__ void acc_u4(float* f, uint4 v) {
    float2 p;
    p = __half22float2(*reinterpret_cast<__half2*>(&v.x)); f[0] += p.x; f[1] += p.y;
    p = __half22float2(*reinterpret_cast<__half2*>(&v.y)); f[2] += p.x; f[3] += p.y;
    p = __half22float2(*reinterpret_cast<__half2*>(&v.z)); f[4] += p.x; f[5] += p.y;
    p = __half22float2(*reinterpret_cast<__half2*>(&v.w)); f[6] += p.x; f[7] += p.y;
}

// ---------------- CSR phase A (count + scan + dinv/rowptr/cursor) ----------------
__device__ __forceinline__ void grid_bar(int target) {
    __syncthreads();
    if (threadIdx.x == 0) {
        __threadfence();
        atomicAdd(&g_bar, 1);
        while (atomicAdd(&g_bar, 0) < target) __nanosleep(64);
        __threadfence();
    }
    __syncthreads();
}

__global__ __launch_bounds__(256, 4) void k_csr_a(const int* __restrict__ dst) {
    const int B = CSR_BLOCKS;
    int tid = threadIdx.x, b = blockIdx.x;
    int gthreads = B * 256;
    int gt = b * 256 + tid;
    __shared__ int sm[256];

    // P1: degree count
    for (int e = gt; e < N_EDGES; e += gthreads)
        atomicAdd(&g_cnt[dst[e]], 1);
    grid_bar(B);

    // P2a: per-block partial sum over node chunk
    const int CH = (N_NODES + B - 1) / B;          // 196
    int nb = b * CH;
    int ne = nb + CH; if (ne > N_NODES) ne = N_NODES;
    int s = 0;
    for (int i = nb + tid; i < ne; i += 256) s += g_cnt[i];
    sm[tid] = s;
    __syncthreads();
    for (int off = 128; off > 0; off >>= 1) {
        if (tid < off) sm[tid] += sm[tid + off];
        __syncthreads();
    }
    if (tid == 0) g_bsum[b] = sm[0];
    grid_bar(2 * B);

    // P2b: block 0 exclusive-scans the 512 partials
    if (b == 0) {
        int i0 = 2 * tid, i1 = 2 * tid + 1;
        int v0 = (i0 < B) ? g_bsum[i0] : 0;
        int v1 = (i1 < B) ? g_bsum[i1] : 0;
        int tsum = v0 + v1;
        __syncthreads();
        sm[tid] = tsum;
        __syncthreads();
        for (int off = 1; off < 256; off <<= 1) {
            int x = (tid >= off) ? sm[tid - off] : 0;
            __syncthreads();
            sm[tid] += x;
            __syncthreads();
        }
        int run = (tid == 0) ? 0 : sm[tid - 1];
        if (i0 < B) g_bsum[i0] = run;
        run += v0;
        if (i1 < B) g_bsum[i1] = run;
        if (tid == 255) g_rowptr[N_NODES] = sm[255];
    }
    grid_bar(3 * B);

    // P2c: write rowptr/cursor/dinv for this block's chunk (CH=196 <= 256)
    {
        int cnt_n = ne - nb;
        int myc = 0;
        if (tid < cnt_n) myc = g_cnt[nb + tid];
        __syncthreads();
        sm[tid] = myc;
        __syncthreads();
        for (int off = 1; off < 256; off <<= 1) {
            int x = (tid >= off) ? sm[tid - off] : 0;
            __syncthreads();
            sm[tid] += x;
            __syncthreads();
        }
        if (tid < cnt_n) {
            int run = g_bsum[b] + ((tid == 0) ? 0 : sm[tid - 1]);
            g_rowptr[nb + tid] = run;
            g_cursor[nb + tid] = run;
            g_dinv[nb + tid] = rsqrtf((float)myc + 1.0f);
        }
    }
}

// ---------------- weight packing ([n][k] transposed, fp16) ----------------
__global__ void k_pack1(const float* __restrict__ W1, const float* __restrict__ Ws02,
                        const float* __restrict__ Ws03) {
    int i = blockIdx.x * 256 + threadIdx.x;
    if (i >= 128 * 256) return;
    int n = i >> 8, k = i & 255;
    float v = 0.f;
    if (n < 64)       v = W1[k * 64 + n];
    else if (n < 96)  v = Ws02[k * 32 + (n - 64)];
    else if (n < 112) v = Ws03[k * 16 + (n - 96)];
    g_W1h[i] = __float2half(v);
}

__global__ void k_pack2(const float* __restrict__ W2, const float* __restrict__ Ws13) {
    int i = blockIdx.x * 256 + threadIdx.x;
    if (i >= 64 * 64) return;
    int n = i >> 6, k = i & 63;
    float v = 0.f;
    if (n < 32)      v = W2[k * 32 + n];
    else if (n < 48) v = Ws13[k * 16 + (n - 32)];
    g_W2h[i] = __float2half(v);
}

// ---------------- Fused GEMM1 + CSR fill ----------------
// blocks [0, G1_BLOCKS): mma.sync fp16 GEMM x[100k,256] @ Wcat1[256,128]
// blocks [G1_BLOCKS, G1_BLOCKS+FILL_BLOCKS): edge scatter fill of g_col
#define G1_A 0
#define G1_B 16384
#define G1_TOTAL 32768

__global__ __launch_bounds__(256, 2) void k_g1fill(const float* __restrict__ X,
                                                   const int* __restrict__ src,
                                                   const int* __restrict__ dst) {
    if (blockIdx.x >= G1_BLOCKS) {
        // ---- fill part ----
        int fb = blockIdx.x - G1_BLOCKS;
        int gthreads = FILL_BLOCKS * 256;
        for (int e = fb * 256 + threadIdx.x; e < N_EDGES; e += gthreads) {
            int d = dst[e];
            int p = atomicAdd(&g_cursor[d], 1);
            if (p < N_EDGES) g_col[p] = src[e];  // clamp guards profiler replay
        }
        return;
    }
    // ---- GEMM part ----
    extern __shared__ __align__(1024) char smem[];
    uint32_t sb = smem_u32(smem);
    int tid = threadIdx.x, wid = tid >> 5, lane = tid & 31;
    int rowBase = blockIdx.x * 128;
    int mw = wid >> 1, nw = wid & 1;          // 4 m-warps x 2 n-warps
    int g = lane >> 2, t4 = lane & 3;

    float c[2][8][4];
    #pragma unroll
    for (int a = 0; a < 2; a++)
        #pragma unroll
        for (int b = 0; b < 8; b++)
            #pragma unroll
            for (int d = 0; d < 4; d++) c[a][b][d] = 0.f;

    int lr = lane & 7, lts = lane >> 3;
    int aRow = tid >> 4, aKq = (tid & 15) * 4;

    for (int ch = 0; ch < 4; ch++) {
        int kt = ch * 64;
        float4 v[8];
        #pragma unroll
        for (int i = 0; i < 8; i++) {
            int row = aRow + i * 16;
            int gr = rowBase + row;
            v[i] = (gr < N_NODES) ? *(const float4*)(X + (size_t)gr * 256 + kt + aKq)
                                  : make_float4(0.f, 0.f, 0.f, 0.f);
        }
        __syncthreads();
        #pragma unroll
        for (int i = 0; i < 8; i++) {
            int row = aRow + i * 16;
            uint32_t p0 = pk_h2(__float2half(v[i].x), __float2half(v[i].y));
            uint32_t p1 = pk_h2(__float2half(v[i].z), __float2half(v[i].w));
            uint32_t off = SW128(row * 128 + aKq * 2);
            *(uint2*)(smem + G1_A + off) = make_uint2(p0, p1);
        }
        #pragma unroll
        for (int i = 0; i < 4; i++) {
            int gidx = tid + i * 256;               // 0..1023
            int n = gidx >> 3, q = gidx & 7;
            uint32_t off = SW128(n * 128 + q * 16);
            size_t gb = (size_t)n * 512 + (size_t)(kt + q * 8) * 2;
            *(uint4*)(smem + G1_B + off) = *(const uint4*)((const char*)g_W1h + gb);
        }
        __syncthreads();

        #pragma unroll
        for (int ks = 0; ks < 4; ks++) {
            int k0 = ks * 16;
            uint32_t aF[2][4];
            #pragma unroll
            for (int mt = 0; mt < 2; mt++) {
                int row = mw * 32 + mt * 16 + lr + ((lts & 1) << 3);
                int kk = k0 + ((lts >> 1) << 3);
                uint32_t off = SW128(row * 128 + kk * 2);
                ldsm_x4(sb + G1_A + off, aF[mt]);
            }
            #pragma unroll
            for (int q = 0; q < 2; q++) {
                int n = nw * 64 + (q * 4 + lts) * 8 + lr;
                uint32_t offLo = SW128(n * 128 + k0 * 2);
                uint32_t offHi = SW128(n * 128 + (k0 + 8) * 2);
                uint32_t t0[4], t1[4];
                ldsm_x4(sb + G1_B + offLo, t0);
                ldsm_x4(sb + G1_B + offHi, t1);
                #pragma unroll
                for (int j = 0; j < 4; j++) {
                    uint32_t bf[2] = { t0[j], t1[j] };
                    #pragma unroll
                    for (int mt = 0; mt < 2; mt++)
                        mma16816h(c[mt][q * 4 + j], aF[mt], bf);
                }
            }
        }
    }

    // epilogue: hs1 fp16, s02/s03 fp32
    #pragma unroll
    for (int mt = 0; mt < 2; mt++) {
        int r0 = rowBase + mw * 32 + mt * 16 + g;
        int r1 = r0 + 8;
        float dv0 = (r0 < N_NODES) ? g_dinv[r0] : 0.f;
        float dv1 = (r1 < N_NODES) ? g_dinv[r1] : 0.f;
        #pragma unroll
        for (int j = 0; j < 8; j++) {
            int col = nw * 64 + j * 8 + t4 * 2;
            float c0 = c[mt][j][0], c1 = c[mt][j][1];
            float c2 = c[mt][j][2], c3 = c[mt][j][3];
            if (r0 < N_NODES) {
                if (col < 64) {
                    *(__half2*)(g_hs1h + (size_t)r0 * 64 + col) = __floats2half2_rn(dv0 * c0, dv0 * c1);
                } else if (col < 96)  *(float2*)(g_s02 + (size_t)r0 * 32 + (col - 64)) = make_float2(c0, c1);
                else if (col < 112)   *(float2*)(g_s03 + (size_t)r0 * 16 + (col - 96)) = make_float2(c0, c1);
            }
            if (r1 < N_NODES) {
                if (col < 64) {
                    *(__half2*)(g_hs1h + (size_t)r1 * 64 + col) = __floats2half2_rn(dv1 * c2, dv1 * c3);
                } else if (col < 96)  *(float2*)(g_s02 + (size_t)r1 * 32 + (col - 64)) = make_float2(c2, c3);
                else if (col < 112)   *(float2*)(g_s03 + (size_t)r1 * 16 + (col - 96)) = make_float2(c2, c3);
            }
        }
    }
}

// ---------------- GEMM2 (mma.sync fp16): x1[100k,64] @ Wcat2[64,64] ----------------
#define G2_A 0
#define G2_B 16384
#define G2_TOTAL 24576

__global__ __launch_bounds__(256, 2) void k_gemm2_mma() {
    extern __shared__ __align__(1024) char smem[];
    uint32_t sb = smem_u32(smem);
    int tid = threadIdx.x, wid = tid >> 5, lane = tid & 31;
    int rowBase = blockIdx.x * 128;
    int mw = wid >> 1, nw = wid & 1;
    int g = lane >> 2, t4 = lane & 3;
    int lr = lane & 7, lts = lane >> 3;

    float c[2][4][4];
    #pragma unroll
    for (int a = 0; a < 2; a++)
        #pragma unroll
        for (int b = 0; b < 4; b++)
            #pragma unroll
            for (int d = 0; d < 4; d++) c[a][b][d] = 0.f;

    #pragma unroll
    for (int i = 0; i < 4; i++) {
        int gidx = tid + i * 256;
        int row = gidx >> 3, q = gidx & 7;
        int gr = rowBase + row;
        uint32_t off = SW128(row * 128 + q * 16);
        if (gr < N_NODES) {
            *(uint4*)(smem + G2_A + off) = *(const uint4*)((const char*)g_x1h + (size_t)gr * 128 + (size_t)q * 16);
        } else {
            *(uint4*)(smem + G2_A + off) = make_uint4(0, 0, 0, 0);
        }
    }
    #pragma unroll
    for (int i = 0; i < 2; i++) {
        int gidx = tid + i * 256;
        int n = gidx >> 3, q = gidx & 7;
        uint32_t off = SW128(n * 128 + q * 16);
        *(uint4*)(smem + G2_B + off) = *(const uint4*)((const char*)g_W2h + (size_t)n * 128 + (size_t)q * 16);
    }
    __syncthreads();

    #pragma unroll
    for (int ks = 0; ks < 4; ks++) {
        int k0 = ks * 16;
        uint32_t aF[2][4], bF[4][2];
        #pragma unroll
        for (int mt = 0; mt < 2; mt++) {
            int row = mw * 32 + mt * 16 + lr + ((lts & 1) << 3);
            int kk = k0 + ((lts >> 1) << 3);
            uint32_t off = SW128(row * 128 + kk * 2);
            ldsm_x4(sb + G2_A + off, aF[mt]);
        }
        {
            int n = nw * 32 + lts * 8 + lr;
            uint32_t offLo = SW128(n * 128 + k0 * 2);
            uint32_t offHi = SW128(n * 128 + (k0 + 8) * 2);
            uint32_t t0[4], t1[4];
            ldsm_x4(sb + G2_B + offLo, t0);
            ldsm_x4(sb + G2_B + offHi, t1);
            #pragma unroll
            for (int j = 0; j < 4; j++) { bF[j][0] = t0[j]; bF[j][1] = t1[j]; }
        }
        #pragma unroll
        for (int mt = 0; mt < 2; mt++)
            #pragma unroll
            for (int j = 0; j < 4; j++)
                mma16816h(c[mt][j], aF[mt], bF[j]);
    }

    #pragma unroll
    for (int mt = 0; mt < 2; mt++) {
        int r0 = rowBase + mw * 32 + mt * 16 + g;
        int r1 = r0 + 8;
        float dv0 = (r0 < N_NODES) ? g_dinv[r0] : 0.f;
        float dv1 = (r1 < N_NODES) ? g_dinv[r1] : 0.f;
        #pragma unroll
        for (int j = 0; j < 4; j++) {
            int col = nw * 32 + j * 8 + t4 * 2;
            float c0 = c[mt][j][0], c1 = c[mt][j][1];
            float c2 = c[mt][j][2], c3 = c[mt][j][3];
            if (r0 < N_NODES) {
                if (col < 32) {
                    *(__half2*)(g_hs2h + (size_t)r0 * 32 + col) = __floats2half2_rn(dv0 * c0, dv0 * c1);
                } else if (col < 48) *(float2*)(g_s13 + (size_t)r0 * 16 + (col - 32)) = make_float2(c0, c1);
            }
            if (r1 < N_NODES) {
                if (col < 32) {
                    *(__half2*)(g_hs2h + (size_t)r1 * 32 + col) = __floats2half2_rn(dv1 * c2, dv1 * c3);
                } else if (col < 48) *(float2*)(g_s13 + (size_t)r1 * 16 + (col - 32)) = make_float2(c2, c3);
            }
        }
    }
}

// ---------------- GEMM 3 (small): x2[100k,32] @ W3[32,16] ----------------
__global__ __launch_bounds__(256) void k_gemm3(const float* __restrict__ W3) {
    __shared__ float sW[32 * 16];
    int tid = threadIdx.x;
    sW[tid] = W3[tid];
    sW[tid + 256] = W3[tid + 256];
    __syncthreads();
    int gid = blockIdx.x * 256 + tid;
    int node = gid >> 4, cc = gid & 15;
    const __half2* xr = (const __half2*)(g_x2h + (size_t)node * 32);
    float acc = 0.f;
    #pragma unroll
    for (int k = 0; k < 16; k++) {
        float2 p = __half22float2(xr[k]);
        acc += p.x * sW[(2 * k) * 16 + cc] + p.y * sW[(2 * k + 1) * 16 + cc];
    }
    g_hs3h[gid] = __float2half(g_dinv[node] * acc);
}

// ---------------- shfl-free warp-cooperative CSR aggregation (fp16 rows) ----------------
// agg1: DIM=64 fp16 -> 8 uint4/row. 4 groups of 8 lanes; each group walks every 4th edge.
__global__ __launch_bounds__(256) void k_agg1(const float* __restrict__ b1) {
    int wid = threadIdx.x >> 5, lane = threadIdx.x & 31;
    int node = blockIdx.x * 8 + wid;
    int oc = lane >> 3, fl = lane & 7;
    const uint4* hs = (const uint4*)g_hs1h;
    int beg = g_rowptr[node], end = g_rowptr[node + 1];
    float f[8] = {0.f, 0.f, 0.f, 0.f, 0.f, 0.f, 0.f, 0.f};
    if (oc == 0) acc_u4(f, hs[(size_t)node * 8 + fl]);   // self term (prescaled)
    int e = beg + oc;
    for (; e + 4 < end; e += 8) {
        int j0 = g_col[e];
        int j1 = g_col[e + 4];
        acc_u4(f, hs[(size_t)j0 * 8 + fl]);
        acc_u4(f, hs[(size_t)j1 * 8 + fl]);
    }
    if (e < end) acc_u4(f, hs[(size_t)g_col[e] * 8 + fl]);
    #pragma unroll
    for (int i = 0; i < 8; i++) {
        f[i] += __shfl_xor_sync(0xffffffffu, f[i], 8);
        f[i] += __shfl_xor_sync(0xffffffffu, f[i], 16);
    }
    if (oc == 0) {
        float dv = g_dinv[node];
        float4 b0 = ((const float4*)b1)[2 * fl];
        float4 b4 = ((const float4*)b1)[2 * fl + 1];
        float o[8];
        o[0] = fmaxf(dv * f[0] + b0.x, 0.f); o[1] = fmaxf(dv * f[1] + b0.y, 0.f);
        o[2] = fmaxf(dv * f[2] + b0.z, 0.f); o[3] = fmaxf(dv * f[3] + b0.w, 0.f);
        o[4] = fmaxf(dv * f[4] + b4.x, 0.f); o[5] = fmaxf(dv * f[5] + b4.y, 0.f);
        o[6] = fmaxf(dv * f[6] + b4.z, 0.f); o[7] = fmaxf(dv * f[7] + b4.w, 0.f);
        uint4 hv;
        uint32_t* hp = (uint32_t*)&hv;
        #pragma unroll
        for (int q = 0; q < 4; q++) {
            __half2 p = __floats2half2_rn(o[2 * q], o[2 * q + 1]);
            hp[q] = *reinterpret_cast<uint32_t*>(&p);
        }
        ((uint4*)g_x1h)[(size_t)node * 8 + fl] = hv;
    }
}

// agg2: DIM=32 fp16 -> 4 uint4/row. 8 groups of 4 lanes, stride 8.
__global__ __launch_bounds__(256) void k_agg2(const float* __restrict__ b2,
                                              const float* __restrict__ bs02) {
    int wid = threadIdx.x >> 5, lane = threadIdx.x & 31;
    int node = blockIdx.x * 8 + wid;
    int oc = lane >> 2, fl = lane & 3;
    const uint4* hs = (const uint4*)g_hs2h;
    int beg = g_rowptr[node], end = g_rowptr[node + 1];
    float f[8] = {0.f, 0.f, 0.f, 0.f, 0.f, 0.f, 0.f, 0.f};
    if (oc == 0) acc_u4(f, hs[(size_t)node * 4 + fl]);
    int e = beg + oc;
    for (; e + 8 < end; e += 16) {
        int j0 = g_col[e];
        int j1 = g_col[e + 8];
        acc_u4(f, hs[(size_t)j0 * 4 + fl]);
        acc_u4(f, hs[(size_t)j1 * 4 + fl]);
    }
    if (e < end) acc_u4(f, hs[(size_t)g_col[e] * 4 + fl]);
    #pragma unroll
    for (int i = 0; i < 8; i++) {
        f[i] += __shfl_xor_sync(0xffffffffu, f[i], 4);
        f[i] += __shfl_xor_sync(0xffffffffu, f[i], 8);
        f[i] += __shfl_xor_sync(0xffffffffu, f[i], 16);
    }
    if (oc == 0) {
        float dv = g_dinv[node];
        float4 b0 = ((const float4*)b2)[2 * fl];
        float4 b4 = ((const float4*)b2)[2 * fl + 1];
        float4 sb0 = ((const float4*)bs02)[2 * fl];
        float4 sb4 = ((const float4*)bs02)[2 * fl + 1];
        float4 s0 = ((const float4*)g_s02)[(size_t)node * 8 + 2 * fl];
        float4 s4 = ((const float4*)g_s02)[(size_t)node * 8 + 2 * fl + 1];
        float o[8];
        o[0] = fmaxf(dv * f[0] + b0.x + s0.x + sb0.x, 0.f);
        o[1] = fmaxf(dv * f[1] + b0.y + s0.y + sb0.y, 0.f);
        o[2] = fmaxf(dv * f[2] + b0.z + s0.z + sb0.z, 0.f);
        o[3] = fmaxf(dv * f[3] + b0.w + s0.w + sb0.w, 0.f);
        o[4] = fmaxf(dv * f[4] + b4.x + s4.x + sb4.x, 0.f);
        o[5] = fmaxf(dv * f[5] + b4.y + s4.y + sb4.y, 0.f);
        o[6] = fmaxf(dv * f[6] + b4.z + s4.z + sb4.z, 0.f);
        o[7] = fmaxf(dv * f[7] + b4.w + s4.w + sb4.w, 0.f);
        uint4 hv;
        uint32_t* hp = (uint32_t*)&hv;
        #pragma unroll
        for (int q = 0; q < 4; q++) {
            __half2 p = __floats2half2_rn(o[2 * q], o[2 * q + 1]);
            hp[q] = *reinterpret_cast<uint32_t*>(&p);
        }
        ((uint4*)g_x2h)[(size_t)node * 4 + fl] = hv;
    }
}

// agg3: DIM=16 fp16 -> 2 uint4/row. 16 groups of 2 lanes, stride 16. Fused head.
__global__ __launch_bounds__(256) void k_agg3(const float* __restrict__ b3,
                                              const float* __restrict__ bs03,
                                              const float* __restrict__ bs13,
                                              const float* __restrict__ Wout,
                                              const float* __restrict__ bout,
                                              float* __restrict__ out) {
    int wid = threadIdx.x >> 5, lane = threadIdx.x & 31;
    int node = blockIdx.x * 8 + wid;
    int oc = lane >> 1, fl = lane & 1;
    const uint4* hs = (const uint4*)g_hs3h;
    int beg = g_rowptr[node], end = g_rowptr[node + 1];
    float f[8] = {0.f, 0.f, 0.f, 0.f, 0.f, 0.f, 0.f, 0.f};
    if (oc == 0) acc_u4(f, hs[(size_t)node * 2 + fl]);
    int e = beg + oc;
    for (; e + 16 < end; e += 32) {
        int j0 = g_col[e];
        int j1 = g_col[e + 16];
        acc_u4(f, hs[(size_t)j0 * 2 + fl]);
        acc_u4(f, hs[(size_t)j1 * 2 + fl]);
    }
    if (e < end) acc_u4(f, hs[(size_t)g_col[e] * 2 + fl]);
    #pragma unroll
    for (int i = 0; i < 8; i++) {
        f[i] += __shfl_xor_sync(0xffffffffu, f[i], 2);
        f[i] += __shfl_xor_sync(0xffffffffu, f[i], 4);
        f[i] += __shfl_xor_sync(0xffffffffu, f[i], 8);
        f[i] += __shfl_xor_sync(0xffffffffu, f[i], 16);
    }
    float dv = g_dinv[node];
    float4 b0 = ((const float4*)b3)[2 * fl];
    float4 b4 = ((const float4*)b3)[2 * fl + 1];
    float4 q0 = ((const float4*)bs03)[2 * fl];
    float4 q4 = ((const float4*)bs03)[2 * fl + 1];
    float4 r0 = ((const float4*)bs13)[2 * fl];
    float4 r4 = ((const float4*)bs13)[2 * fl + 1];
    float4 s0 = ((const float4*)g_s03)[(size_t)node * 4 + 2 * fl];
    float4 s4 = ((const float4*)g_s03)[(size_t)node * 4 + 2 * fl + 1];
    float4 u0 = ((const float4*)g_s13)[(size_t)node * 4 + 2 * fl];
    float4 u4 = ((const float4*)g_s13)[(size_t)node * 4 + 2 * fl + 1];
    float4 w0 = ((const float4*)Wout)[2 * fl];
    float4 w4 = ((const float4*)Wout)[2 * fl + 1];
    float t0 = fmaxf(dv * f[0] + b0.x + s0.x + q0.x + u0.x + r0.x, 0.f);
    float t1 = fmaxf(dv * f[1] + b0.y + s0.y + q0.y + u0.y + r0.y, 0.f);
    float t2 = fmaxf(dv * f[2] + b0.z + s0.z + q0.z + u0.z + r0.z, 0.f);
    float t3 = fmaxf(dv * f[3] + b0.w + s0.w + q0.w + u0.w + r0.w, 0.f);
    float t4v = fmaxf(dv * f[4] + b4.x + s4.x + q4.x + u4.x + r4.x, 0.f);
    float t5 = fmaxf(dv * f[5] + b4.y + s4.y + q4.y + u4.y + r4.y, 0.f);
    float t6 = fmaxf(dv * f[6] + b4.z + s4.z + q4.z + u4.z + r4.z, 0.f);
    float t7 = fmaxf(dv * f[7] + b4.w + s4.w + q4.w + u4.w + r4.w, 0.f);
    float v = t0 * w0.x + t1 * w0.y + t2 * w0.z + t3 * w0.w
            + t4v * w4.x + t5 * w4.y + t6 * w4.z + t7 * w4.w;
    v += __shfl_xor_sync(0xffffffffu, v, 1);
    if (lane == 0) out[node] = 1.f / (1.f + __expf(-(v + bout[0])));
}

// ---------------- launch ----------------
extern "C" void kernel_launch(void* const* d_in, const int* in_sizes, int n_in,
                              void* d_out, int out_size) {
    const float* x    = (const float*)d_in[0];
    const int*   ei   = (const int*)d_in[1];
    const float* W1   = (const float*)d_in[2];
    const float* b1   = (const float*)d_in[3];
    const float* W2   = (const float*)d_in[4];
    const float* b2   = (const float*)d_in[5];
    const float* W3   = (const float*)d_in[6];
    const float* b3   = (const float*)d_in[7];
    const float* Ws02 = (const float*)d_in[8];
    const float* bs02 = (const float*)d_in[9];
    const float* Ws03 = (const float*)d_in[10];
    const float* bs03 = (const float*)d_in[11];
    const float* Ws13 = (const float*)d_in[12];
    const float* bs13 = (const float*)d_in[13];
    const float* Wout = (const float*)d_in[14];
    const float* bout = (const float*)d_in[15];
    float* out = (float*)d_out;

    const int* src = ei;
    const int* dst = ei + N_EDGES;

    cudaFuncSetAttribute(k_g1fill, cudaFuncAttributeMaxDynamicSharedMemorySize, G1_TOTAL);
    cudaFuncSetAttribute(k_gemm2_mma, cudaFuncAttributeMaxDynamicSharedMemorySize, G2_TOTAL);

    void* p = nullptr;
    cudaGetSymbolAddress(&p, g_cnt);
    cudaMemsetAsync(p, 0, N_NODES * sizeof(int));
    cudaGetSymbolAddress(&p, g_bar);
    cudaMemsetAsync(p, 0, sizeof(int));

    k_csr_a<<<CSR_BLOCKS, 256>>>(dst);                              // 1
    k_pack1<<<(128 * 256 + 255) / 256, 256>>>(W1, Ws02, Ws03);      // 2
    k_pack2<<<(64 * 64 + 255) / 256, 256>>>(W2, Ws13);              // 3
    k_g1fill<<<G1_BLOCKS + FILL_BLOCKS, 256, G1_TOTAL>>>(x, src, dst); // 4 (profiled)
    k_agg1<<<12500, 256>>>(b1);                                     // 5
    k_gemm2_mma<<<(N_NODES + 127) / 128, 256, G2_TOTAL>>>();        // 6
    k_agg2<<<12500, 256>>>(b2, bs02);                               // 7
    k_gemm3<<<(N_NODES * 16 + 255) / 256, 256>>>(W3);               // 8
    k_agg3<<<12500, 256>>>(b3, bs03, bs13, Wout, bout, out);        // 9
}

// round 13
// speedup vs baseline: 1.3885x; 1.0077x over previous
#include <cuda_runtime.h>
#include <cuda_bf16.h>
#include <cuda_fp16.h>
#include <math.h>
#include <stdint.h>

#define N_NODES 100000
#define N_EDGES 3200000
#define CSR_BLOCKS 512

// ---------------- scratch (static __device__, no allocation) ----------------
__device__ int   g_bar;
__device__ int   g_bsum[CSR_BLOCKS];
__device__ int   g_cnt[N_NODES];
__device__ int   g_rowptr[N_NODES + 1];
__device__ int   g_cursor[N_NODES];
__device__ int   g_col[N_EDGES];
__device__ float g_dinv[N_NODES];
__device__ __align__(16) __half g_W1h[128 * 256];   // [n][k] concat W1|Ws02|Ws03 (transposed), fp16
__device__ __align__(16) __half g_W2h[64 * 64];     // [n][k] concat W2|Ws13 (transposed), fp16
__device__ __align__(16) __half g_hs1h[N_NODES * 64];  // fp16: dinv * (x @ W1)
__device__ __align__(16) float  g_s02[N_NODES * 32];   // x @ Ws02
__device__ __align__(16) float  g_s03[N_NODES * 16];   // x @ Ws03
__device__ __align__(16) __half g_x1h[N_NODES * 64];   // fp16 x1
__device__ __align__(16) __half g_hs2h[N_NODES * 32];  // fp16: dinv * (x1 @ W2)
__device__ __align__(16) float  g_s13[N_NODES * 16];   // x1 @ Ws13
__device__ __align__(16) __half g_x2h[N_NODES * 32];   // fp16 x2
__device__ __align__(16) __half g_hs3h[N_NODES * 16];  // fp16: dinv * (x2 @ W3)

// ---------------- helpers ----------------
__device__ __forceinline__ uint32_t smem_u32(const void* p) {
    uint32_t a;
    asm("{ .reg .u64 t; cvta.to.shared.u64 t, %1; cvt.u32.u64 %0, t; }" : "=r"(a) : "l"(p));
    return a;
}

#define SW128(o) ((uint32_t)(o) ^ ((((uint32_t)(o)) >> 3) & 0x70u))

__device__ __forceinline__ void ldsm_x4(uint32_t addr, uint32_t* r) {
    asm volatile("ldmatrix.sync.aligned.m8n8.x4.shared.b16 {%0,%1,%2,%3}, [%4];"
                 : "=r"(r[0]), "=r"(r[1]), "=r"(r[2]), "=r"(r[3]) : "r"(addr));
}

// fp16 x fp16 -> fp32 accumulate
__device__ __forceinline__ void mma16816h(float* c, const uint32_t* a, const uint32_t* b) {
    asm volatile(
        "mma.sync.aligned.m16n8k16.row.col.f32.f16.f16.f32 "
        "{%0,%1,%2,%3}, {%4,%5,%6,%7}, {%8,%9}, {%0,%1,%2,%3};"
        : "+f"(c[0]), "+f"(c[1]), "+f"(c[2]), "+f"(c[3])
        : "r"(a[0]), "r"(a[1]), "r"(a[2]), "r"(a[3]), "r"(b[0]), "r"(b[1]));
}

__device__ __forceinline__ uint32_t pk_h2(__half a, __half b) {
    __half2 t;
    t.x = a; t.y = b;
    return *reinterpret_cast<uint32_t*>(&t);
}

__device__ __forceinline__ void acc_u4(float* f, uint4 v) {
    float2 p;
    p = __half22float2(*reinterpret_cast<__half2*>(&v.x)); f[0] += p.x; f[1] += p.y;
    p = __half22float2(*reinterpret_cast<__half2*>(&v.y)); f[2] += p.x; f[3] += p.y;
    p = __half22float2(*reinterpret_cast<__half2*>(&v.z)); f[4] += p.x; f[5] += p.y;
    p = __half22float2(*reinterpret_cast<__half2*>(&v.w)); f[6] += p.x; f[7] += p.y;
}

// ---------------- CSR phase A (count + scan + dinv/rowptr/cursor) ----------------
__device__ __forceinline__ void grid_bar(int target) {
    __syncthreads();
    if (threadIdx.x == 0) {
        __threadfence();
        atomicAdd(&g_bar, 1);
        while (atomicAdd(&g_bar, 0) < target) __nanosleep(64);
        __threadfence();
    }
    __syncthreads();
}

__global__ __launch_bounds__(256, 4) void k_csr_a(const int* __restrict__ dst) {
    const int B = CSR_BLOCKS;
    int tid = threadIdx.x, b = blockIdx.x;
    int gthreads = B * 256;
    int gt = b * 256 + tid;
    __shared__ int sm[256];

    // P1: degree count (int4 vectorized: 4 edges per load, 4x MLP)
    {
        const int4* dst4 = (const int4*)dst;
        const int N4 = N_EDGES / 4;  // 800000
        for (int e = gt; e < N4; e += gthreads) {
            int4 d = dst4[e];
            atomicAdd(&g_cnt[d.x], 1);
            atomicAdd(&g_cnt[d.y], 1);
            atomicAdd(&g_cnt[d.z], 1);
            atomicAdd(&g_cnt[d.w], 1);
        }
    }
    grid_bar(B);

    // P2a: per-block partial sum over node chunk
    const int CH = (N_NODES + B - 1) / B;          // 196
    int nb = b * CH;
    int ne = nb + CH; if (ne > N_NODES) ne = N_NODES;
    int s = 0;
    for (int i = nb + tid; i < ne; i += 256) s += g_cnt[i];
    sm[tid] = s;
    __syncthreads();
    for (int off = 128; off > 0; off >>= 1) {
        if (tid < off) sm[tid] += sm[tid + off];
        __syncthreads();
    }
    if (tid == 0) g_bsum[b] = sm[0];
    grid_bar(2 * B);

    // P2b: block 0 exclusive-scans the 512 partials
    if (b == 0) {
        int i0 = 2 * tid, i1 = 2 * tid + 1;
        int v0 = (i0 < B) ? g_bsum[i0] : 0;
        int v1 = (i1 < B) ? g_bsum[i1] : 0;
        int tsum = v0 + v1;
        __syncthreads();
        sm[tid] = tsum;
        __syncthreads();
        for (int off = 1; off < 256; off <<= 1) {
            int x = (tid >= off) ? sm[tid - off] : 0;
            __syncthreads();
            sm[tid] += x;
            __syncthreads();
        }
        int run = (tid == 0) ? 0 : sm[tid - 1];
        if (i0 < B) g_bsum[i0] = run;
        run += v0;
        if (i1 < B) g_bsum[i1] = run;
        if (tid == 255) g_rowptr[N_NODES] = sm[255];
    }
    grid_bar(3 * B);

    // P2c: write rowptr/cursor/dinv for this block's chunk (CH=196 <= 256)
    {
        int cnt_n = ne - nb;
        int myc = 0;
        if (tid < cnt_n) myc = g_cnt[nb + tid];
        __syncthreads();
        sm[tid] = myc;
        __syncthreads();
        for (int off = 1; off < 256; off <<= 1) {
            int x = (tid >= off) ? sm[tid - off] : 0;
            __syncthreads();
            sm[tid] += x;
            __syncthreads();
        }
        if (tid < cnt_n) {
            int run = g_bsum[b] + ((tid == 0) ? 0 : sm[tid - 1]);
            g_rowptr[nb + tid] = run;
            g_cursor[nb + tid] = run;
            g_dinv[nb + tid] = rsqrtf((float)myc + 1.0f);
        }
    }
}

// ---------------- CSR fill (standalone, int4 vectorized, full occupancy) ----------------
__global__ __launch_bounds__(256) void k_fill(const int* __restrict__ src,
                                              const int* __restrict__ dst) {
    int i = blockIdx.x * 256 + threadIdx.x;     // int4 index; grid exact 3125
    const int4* s4 = (const int4*)src;
    const int4* d4 = (const int4*)dst;
    int4 d = d4[i];
    int4 s = s4[i];
    int p0 = atomicAdd(&g_cursor[d.x], 1);
    int p1 = atomicAdd(&g_cursor[d.y], 1);
    int p2 = atomicAdd(&g_cursor[d.z], 1);
    int p3 = atomicAdd(&g_cursor[d.w], 1);
    if (p0 < N_EDGES) g_col[p0] = s.x;          // clamp guards profiler replay
    if (p1 < N_EDGES) g_col[p1] = s.y;
    if (p2 < N_EDGES) g_col[p2] = s.z;
    if (p3 < N_EDGES) g_col[p3] = s.w;
}

// ---------------- weight packing ([n][k] transposed, fp16) ----------------
__global__ void k_pack1(const float* __restrict__ W1, const float* __restrict__ Ws02,
                        const float* __restrict__ Ws03) {
    int i = blockIdx.x * 256 + threadIdx.x;
    if (i >= 128 * 256) return;
    int n = i >> 8, k = i & 255;
    float v = 0.f;
    if (n < 64)       v = W1[k * 64 + n];
    else if (n < 96)  v = Ws02[k * 32 + (n - 64)];
    else if (n < 112) v = Ws03[k * 16 + (n - 96)];
    g_W1h[i] = __float2half(v);
}

__global__ void k_pack2(const float* __restrict__ W2, const float* __restrict__ Ws13) {
    int i = blockIdx.x * 256 + threadIdx.x;
    if (i >= 64 * 64) return;
    int n = i >> 6, k = i & 63;
    float v = 0.f;
    if (n < 32)      v = W2[k * 32 + n];
    else if (n < 48) v = Ws13[k * 16 + (n - 32)];
    g_W2h[i] = __float2half(v);
}

// ---------------- GEMM1 (mma.sync fp16): x[100k,256] @ Wcat1[256,128] ----------------
#define G1_A 0
#define G1_B 16384
#define G1_TOTAL 32768

__global__ __launch_bounds__(256, 2) void k_gemm1_mma(const float* __restrict__ X) {
    extern __shared__ __align__(1024) char smem[];
    uint32_t sb = smem_u32(smem);
    int tid = threadIdx.x, wid = tid >> 5, lane = tid & 31;
    int rowBase = blockIdx.x * 128;
    int mw = wid >> 1, nw = wid & 1;          // 4 m-warps x 2 n-warps
    int g = lane >> 2, t4 = lane & 3;

    float c[2][8][4];
    #pragma unroll
    for (int a = 0; a < 2; a++)
        #pragma unroll
        for (int b = 0; b < 8; b++)
            #pragma unroll
            for (int d = 0; d < 4; d++) c[a][b][d] = 0.f;

    int lr = lane & 7, lts = lane >> 3;
    int aRow = tid >> 4, aKq = (tid & 15) * 4;

    for (int ch = 0; ch < 4; ch++) {
        int kt = ch * 64;
        float4 v[8];
        #pragma unroll
        for (int i = 0; i < 8; i++) {
            int row = aRow + i * 16;
            int gr = rowBase + row;
            v[i] = (gr < N_NODES) ? *(const float4*)(X + (size_t)gr * 256 + kt + aKq)
                                  : make_float4(0.f, 0.f, 0.f, 0.f);
        }
        __syncthreads();
        #pragma unroll
        for (int i = 0; i < 8; i++) {
            int row = aRow + i * 16;
            uint32_t p0 = pk_h2(__float2half(v[i].x), __float2half(v[i].y));
            uint32_t p1 = pk_h2(__float2half(v[i].z), __float2half(v[i].w));
            uint32_t off = SW128(row * 128 + aKq * 2);
            *(uint2*)(smem + G1_A + off) = make_uint2(p0, p1);
        }
        #pragma unroll
        for (int i = 0; i < 4; i++) {
            int gidx = tid + i * 256;               // 0..1023
            int n = gidx >> 3, q = gidx & 7;
            uint32_t off = SW128(n * 128 + q * 16);
            size_t gb = (size_t)n * 512 + (size_t)(kt + q * 8) * 2;
            *(uint4*)(smem + G1_B + off) = *(const uint4*)((const char*)g_W1h + gb);
        }
        __syncthreads();

        #pragma unroll
        for (int ks = 0; ks < 4; ks++) {
            int k0 = ks * 16;
            uint32_t aF[2][4];
            #pragma unroll
            for (int mt = 0; mt < 2; mt++) {
                int row = mw * 32 + mt * 16 + lr + ((lts & 1) << 3);
                int kk = k0 + ((lts >> 1) << 3);
                uint32_t off = SW128(row * 128 + kk * 2);
                ldsm_x4(sb + G1_A + off, aF[mt]);
            }
            #pragma unroll
            for (int q = 0; q < 2; q++) {
                int n = nw * 64 + (q * 4 + lts) * 8 + lr;
                uint32_t offLo = SW128(n * 128 + k0 * 2);
                uint32_t offHi = SW128(n * 128 + (k0 + 8) * 2);
                uint32_t t0[4], t1[4];
                ldsm_x4(sb + G1_B + offLo, t0);
                ldsm_x4(sb + G1_B + offHi, t1);
                #pragma unroll
                for (int j = 0; j < 4; j++) {
                    uint32_t bf[2] = { t0[j], t1[j] };
                    #pragma unroll
                    for (int mt = 0; mt < 2; mt++)
                        mma16816h(c[mt][q * 4 + j], aF[mt], bf);
                }
            }
        }
    }

    // epilogue: hs1 fp16, s02/s03 fp32
    #pragma unroll
    for (int mt = 0; mt < 2; mt++) {
        int r0 = rowBase + mw * 32 + mt * 16 + g;
        int r1 = r0 + 8;
        float dv0 = (r0 < N_NODES) ? g_dinv[r0] : 0.f;
        float dv1 = (r1 < N_NODES) ? g_dinv[r1] : 0.f;
        #pragma unroll
        for (int j = 0; j < 8; j++) {
            int col = nw * 64 + j * 8 + t4 * 2;
            float c0 = c[mt][j][0], c1 = c[mt][j][1];
            float c2 = c[mt][j][2], c3 = c[mt][j][3];
            if (r0 < N_NODES) {
                if (col < 64) {
                    *(__half2*)(g_hs1h + (size_t)r0 * 64 + col) = __floats2half2_rn(dv0 * c0, dv0 * c1);
                } else if (col < 96)  *(float2*)(g_s02 + (size_t)r0 * 32 + (col - 64)) = make_float2(c0, c1);
                else if (col < 112)   *(float2*)(g_s03 + (size_t)r0 * 16 + (col - 96)) = make_float2(c0, c1);
            }
            if (r1 < N_NODES) {
                if (col < 64) {
                    *(__half2*)(g_hs1h + (size_t)r1 * 64 + col) = __floats2half2_rn(dv1 * c2, dv1 * c3);
                } else if (col < 96)  *(float2*)(g_s02 + (size_t)r1 * 32 + (col - 64)) = make_float2(c2, c3);
                else if (col < 112)   *(float2*)(g_s03 + (size_t)r1 * 16 + (col - 96)) = make_float2(c2, c3);
            }
        }
    }
}

// ---------------- GEMM2 (mma.sync fp16): x1[100k,64] @ Wcat2[64,64] ----------------
#define G2_A 0
#define G2_B 16384
#define G2_TOTAL 24576

__global__ __launch_bounds__(256, 2) void k_gemm2_mma() {
    extern __shared__ __align__(1024) char smem[];
    uint32_t sb = smem_u32(smem);
    int tid = threadIdx.x, wid = tid >> 5, lane = tid & 31;
    int rowBase = blockIdx.x * 128;
    int mw = wid >> 1, nw = wid & 1;
    int g = lane >> 2, t4 = lane & 3;
    int lr = lane & 7, lts = lane >> 3;

    float c[2][4][4];
    #pragma unroll
    for (int a = 0; a < 2; a++)
        #pragma unroll
        for (int b = 0; b < 4; b++)
            #pragma unroll
            for (int d = 0; d < 4; d++) c[a][b][d] = 0.f;

    #pragma unroll
    for (int i = 0; i < 4; i++) {
        int gidx = tid + i * 256;
        int row = gidx >> 3, q = gidx & 7;
        int gr = rowBase + row;
        uint32_t off = SW128(row * 128 + q * 16);
        if (gr < N_NODES) {
            *(uint4*)(smem + G2_A + off) = *(const uint4*)((const char*)g_x1h + (size_t)gr * 128 + (size_t)q * 16);
        } else {
            *(uint4*)(smem + G2_A + off) = make_uint4(0, 0, 0, 0);
        }
    }
    #pragma unroll
    for (int i = 0; i < 2; i++) {
        int gidx = tid + i * 256;
        int n = gidx >> 3, q = gidx & 7;
        uint32_t off = SW128(n * 128 + q * 16);
        *(uint4*)(smem + G2_B + off) = *(const uint4*)((const char*)g_W2h + (size_t)n * 128 + (size_t)q * 16);
    }
    __syncthreads();

    #pragma unroll
    for (int ks = 0; ks < 4; ks++) {
        int k0 = ks * 16;
        uint32_t aF[2][4], bF[4][2];
        #pragma unroll
        for (int mt = 0; mt < 2; mt++) {
            int row = mw * 32 + mt * 16 + lr + ((lts & 1) << 3);
            int kk = k0 + ((lts >> 1) << 3);
            uint32_t off = SW128(row * 128 + kk * 2);
            ldsm_x4(sb + G2_A + off, aF[mt]);
        }
        {
            int n = nw * 32 + lts * 8 + lr;
            uint32_t offLo = SW128(n * 128 + k0 * 2);
            uint32_t offHi = SW128(n * 128 + (k0 + 8) * 2);
            uint32_t t0[4], t1[4];
            ldsm_x4(sb + G2_B + offLo, t0);
            ldsm_x4(sb + G2_B + offHi, t1);
            #pragma unroll
            for (int j = 0; j < 4; j++) { bF[j][0] = t0[j]; bF[j][1] = t1[j]; }
        }
        #pragma unroll
        for (int mt = 0; mt < 2; mt++)
            #pragma unroll
            for (int j = 0; j < 4; j++)
                mma16816h(c[mt][j], aF[mt], bF[j]);
    }

    #pragma unroll
    for (int mt = 0; mt < 2; mt++) {
        int r0 = rowBase + mw * 32 + mt * 16 + g;
        int r1 = r0 + 8;
        float dv0 = (r0 < N_NODES) ? g_dinv[r0] : 0.f;
        float dv1 = (r1 < N_NODES) ? g_dinv[r1] : 0.f;
        #pragma unroll
        for (int j = 0; j < 4; j++) {
            int col = nw * 32 + j * 8 + t4 * 2;
            float c0 = c[mt][j][0], c1 = c[mt][j][1];
            float c2 = c[mt][j][2], c3 = c[mt][j][3];
            if (r0 < N_NODES) {
                if (col < 32) {
                    *(__half2*)(g_hs2h + (size_t)r0 * 32 + col) = __floats2half2_rn(dv0 * c0, dv0 * c1);
                } else if (col < 48) *(float2*)(g_s13 + (size_t)r0 * 16 + (col - 32)) = make_float2(c0, c1);
            }
            if (r1 < N_NODES) {
                if (col < 32) {
                    *(__half2*)(g_hs2h + (size_t)r1 * 32 + col) = __floats2half2_rn(dv1 * c2, dv1 * c3);
                } else if (col < 48) *(float2*)(g_s13 + (size_t)r1 * 16 + (col - 32)) = make_float2(c2, c3);
            }
        }
    }
}

// ---------------- GEMM 3 (small): x2[100k,32] @ W3[32,16] ----------------
__global__ __launch_bounds__(256) void k_gemm3(const float* __restrict__ W3) {
    __shared__ float sW[32 * 16];
    int tid = threadIdx.x;
    sW[tid] = W3[tid];
    sW[tid + 256] = W3[tid + 256];
    __syncthreads();
    int gid = blockIdx.x * 256 + tid;
    int node = gid >> 4, cc = gid & 15;
    const __half2* xr = (const __half2*)(g_x2h + (size_t)node * 32);
    float acc = 0.f;
    #pragma unroll
    for (int k = 0; k < 16; k++) {
        float2 p = __half22float2(xr[k]);
        acc += p.x * sW[(2 * k) * 16 + cc] + p.y * sW[(2 * k + 1) * 16 + cc];
    }
    g_hs3h[gid] = __float2half(g_dinv[node] * acc);
}

// ---------------- shfl-free warp-cooperative CSR aggregation (fp16 rows) ----------------
// agg1: DIM=64 fp16 -> 8 uint4/row. 4 groups of 8 lanes; each group walks every 4th edge.
__global__ __launch_bounds__(256) void k_agg1(const float* __restrict__ b1) {
    int wid = threadIdx.x >> 5, lane = threadIdx.x & 31;
    int node = blockIdx.x * 8 + wid;
    int oc = lane >> 3, fl = lane & 7;
    const uint4* hs = (const uint4*)g_hs1h;
    int beg = g_rowptr[node], end = g_rowptr[node + 1];
    float f[8] = {0.f, 0.f, 0.f, 0.f, 0.f, 0.f, 0.f, 0.f};
    if (oc == 0) acc_u4(f, hs[(size_t)node * 8 + fl]);   // self term (prescaled)
    int e = beg + oc;
    for (; e + 4 < end; e += 8) {
        int j0 = g_col[e];
        int j1 = g_col[e + 4];
        acc_u4(f, hs[(size_t)j0 * 8 + fl]);
        acc_u4(f, hs[(size_t)j1 * 8 + fl]);
    }
    if (e < end) acc_u4(f, hs[(size_t)g_col[e] * 8 + fl]);
    #pragma unroll
    for (int i = 0; i < 8; i++) {
        f[i] += __shfl_xor_sync(0xffffffffu, f[i], 8);
        f[i] += __shfl_xor_sync(0xffffffffu, f[i], 16);
    }
    if (oc == 0) {
        float dv = g_dinv[node];
        float4 b0 = ((const float4*)b1)[2 * fl];
        float4 b4 = ((const float4*)b1)[2 * fl + 1];
        float o[8];
        o[0] = fmaxf(dv * f[0] + b0.x, 0.f); o[1] = fmaxf(dv * f[1] + b0.y, 0.f);
        o[2] = fmaxf(dv * f[2] + b0.z, 0.f); o[3] = fmaxf(dv * f[3] + b0.w, 0.f);
        o[4] = fmaxf(dv * f[4] + b4.x, 0.f); o[5] = fmaxf(dv * f[5] + b4.y, 0.f);
        o[6] = fmaxf(dv * f[6] + b4.z, 0.f); o[7] = fmaxf(dv * f[7] + b4.w, 0.f);
        uint4 hv;
        uint32_t* hp = (uint32_t*)&hv;
        #pragma unroll
        for (int q = 0; q < 4; q++) {
            __half2 p = __floats2half2_rn(o[2 * q], o[2 * q + 1]);
            hp[q] = *reinterpret_cast<uint32_t*>(&p);
        }
        ((uint4*)g_x1h)[(size_t)node * 8 + fl] = hv;
    }
}

// agg2: DIM=32 fp16 -> 4 uint4/row. 8 groups of 4 lanes, stride 8.
__global__ __launch_bounds__(256) void k_agg2(const float* __restrict__ b2,
                                              const float* __restrict__ bs02) {
    int wid = threadIdx.x >> 5, lane = threadIdx.x & 31;
    int node = blockIdx.x * 8 + wid;
    int oc = lane >> 2, fl = lane & 3;
    const uint4* hs = (const uint4*)g_hs2h;
    int beg = g_rowptr[node], end = g_rowptr[node + 1];
    float f[8] = {0.f, 0.f, 0.f, 0.f, 0.f, 0.f, 0.f, 0.f};
    if (oc == 0) acc_u4(f, hs[(size_t)node * 4 + fl]);
    int e = beg + oc;
    for (; e + 8 < end; e += 16) {
        int j0 = g_col[e];
        int j1 = g_col[e + 8];
        acc_u4(f, hs[(size_t)j0 * 4 + fl]);
        acc_u4(f, hs[(size_t)j1 * 4 + fl]);
    }
    if (e < end) acc_u4(f, hs[(size_t)g_col[e] * 4 + fl]);
    #pragma unroll
    for (int i = 0; i < 8; i++) {
        f[i] += __shfl_xor_sync(0xffffffffu, f[i], 4);
        f[i] += __shfl_xor_sync(0xffffffffu, f[i], 8);
        f[i] += __shfl_xor_sync(0xffffffffu, f[i], 16);
    }
    if (oc == 0) {
        float dv = g_dinv[node];
        float4 b0 = ((const float4*)b2)[2 * fl];
        float4 b4 = ((const float4*)b2)[2 * fl + 1];
        float4 sb0 = ((const float4*)bs02)[2 * fl];
        float4 sb4 = ((const float4*)bs02)[2 * fl + 1];
        float4 s0 = ((const float4*)g_s02)[(size_t)node * 8 + 2 * fl];
        float4 s4 = ((const float4*)g_s02)[(size_t)node * 8 + 2 * fl + 1];
        float o[8];
        o[0] = fmaxf(dv * f[0] + b0.x + s0.x + sb0.x, 0.f);
        o[1] = fmaxf(dv * f[1] + b0.y + s0.y + sb0.y, 0.f);
        o[2] = fmaxf(dv * f[2] + b0.z + s0.z + sb0.z, 0.f);
        o[3] = fmaxf(dv * f[3] + b0.w + s0.w + sb0.w, 0.f);
        o[4] = fmaxf(dv * f[4] + b4.x + s4.x + sb4.x, 0.f);
        o[5] = fmaxf(dv * f[5] + b4.y + s4.y + sb4.y, 0.f);
        o[6] = fmaxf(dv * f[6] + b4.z + s4.z + sb4.z, 0.f);
        o[7] = fmaxf(dv * f[7] + b4.w + s4.w + sb4.w, 0.f);
        uint4 hv;
        uint32_t* hp = (uint32_t*)&hv;
        #pragma unroll
        for (int q = 0; q < 4; q++) {
            __half2 p = __floats2half2_rn(o[2 * q], o[2 * q + 1]);
            hp[q] = *reinterpret_cast<uint32_t*>(&p);
        }
        ((uint4*)g_x2h)[(size_t)node * 4 + fl] = hv;
    }
}

// agg3: DIM=16 fp16 -> 2 uint4/row. 16 groups of 2 lanes, stride 16. Fused head.
__global__ __launch_bounds__(256) void k_agg3(const float* __restrict__ b3,
                                              const float* __restrict__ bs03,
                                              const float* __restrict__ bs13,
                                              const float* __restrict__ Wout,
                                              const float* __restrict__ bout,
                                              float* __restrict__ out) {
    int wid = threadIdx.x >> 5, lane = threadIdx.x & 31;
    int node = blockIdx.x * 8 + wid;
    int oc = lane >> 1, fl = lane & 1;
    const uint4* hs = (const uint4*)g_hs3h;
    int beg = g_rowptr[node], end = g_rowptr[node + 1];
    float f[8] = {0.f, 0.f, 0.f, 0.f, 0.f, 0.f, 0.f, 0.f};
    if (oc == 0) acc_u4(f, hs[(size_t)node * 2 + fl]);
    int e = beg + oc;
    for (; e + 16 < end; e += 32) {
        int j0 = g_col[e];
        int j1 = g_col[e + 16];
        acc_u4(f, hs[(size_t)j0 * 2 + fl]);
        acc_u4(f, hs[(size_t)j1 * 2 + fl]);
    }
    if (e < end) acc_u4(f, hs[(size_t)g_col[e] * 2 + fl]);
    #pragma unroll
    for (int i = 0; i < 8; i++) {
        f[i] += __shfl_xor_sync(0xffffffffu, f[i], 2);
        f[i] += __shfl_xor_sync(0xffffffffu, f[i], 4);
        f[i] += __shfl_xor_sync(0xffffffffu, f[i], 8);
        f[i] += __shfl_xor_sync(0xffffffffu, f[i], 16);
    }
    float dv = g_dinv[node];
    float4 b0 = ((const float4*)b3)[2 * fl];
    float4 b4 = ((const float4*)b3)[2 * fl + 1];
    float4 q0 = ((const float4*)bs03)[2 * fl];
    float4 q4 = ((const float4*)bs03)[2 * fl + 1];
    float4 r0 = ((const float4*)bs13)[2 * fl];
    float4 r4 = ((const float4*)bs13)[2 * fl + 1];
    float4 s0 = ((const float4*)g_s03)[(size_t)node * 4 + 2 * fl];
    float4 s4 = ((const float4*)g_s03)[(size_t)node * 4 + 2 * fl + 1];
    float4 u0 = ((const float4*)g_s13)[(size_t)node * 4 + 2 * fl];
    float4 u4 = ((const float4*)g_s13)[(size_t)node * 4 + 2 * fl + 1];
    float4 w0 = ((const float4*)Wout)[2 * fl];
    float4 w4 = ((const float4*)Wout)[2 * fl + 1];
    float t0 = fmaxf(dv * f[0] + b0.x + s0.x + q0.x + u0.x + r0.x, 0.f);
    float t1 = fmaxf(dv * f[1] + b0.y + s0.y + q0.y + u0.y + r0.y, 0.f);
    float t2 = fmaxf(dv * f[2] + b0.z + s0.z + q0.z + u0.z + r0.z, 0.f);
    float t3 = fmaxf(dv * f[3] + b0.w + s0.w + q0.w + u0.w + r0.w, 0.f);
    float t4v = fmaxf(dv * f[4] + b4.x + s4.x + q4.x + u4.x + r4.x, 0.f);
    float t5 = fmaxf(dv * f[5] + b4.y + s4.y + q4.y + u4.y + r4.y, 0.f);
    float t6 = fmaxf(dv * f[6] + b4.z + s4.z + q4.z + u4.z + r4.z, 0.f);
    float t7 = fmaxf(dv * f[7] + b4.w + s4.w + q4.w + u4.w + r4.w, 0.f);
    float v = t0 * w0.x + t1 * w0.y + t2 * w0.z + t3 * w0.w
            + t4v * w4.x + t5 * w4.y + t6 * w4.z + t7 * w4.w;
    v += __shfl_xor_sync(0xffffffffu, v, 1);
    if (lane == 0) out[node] = 1.f / (1.f + __expf(-(v + bout[0])));
}

// ---------------- launch ----------------
extern "C" void kernel_launch(void* const* d_in, const int* in_sizes, int n_in,
                              void* d_out, int out_size) {
    const float* x    = (const float*)d_in[0];
    const int*   ei   = (const int*)d_in[1];
    const float* W1   = (const float*)d_in[2];
    const float* b1   = (const float*)d_in[3];
    const float* W2   = (const float*)d_in[4];
    const float* b2   = (const float*)d_in[5];
    const float* W3   = (const float*)d_in[6];
    const float* b3   = (const float*)d_in[7];
    const float* Ws02 = (const float*)d_in[8];
    const float* bs02 = (const float*)d_in[9];
    const float* Ws03 = (const float*)d_in[10];
    const float* bs03 = (const float*)d_in[11];
    const float* Ws13 = (const float*)d_in[12];
    const float* bs13 = (const float*)d_in[13];
    const float* Wout = (const float*)d_in[14];
    const float* bout = (const float*)d_in[15];
    float* out = (float*)d_out;

    const int* src = ei;
    const int* dst = ei + N_EDGES;

    cudaFuncSetAttribute(k_gemm1_mma, cudaFuncAttributeMaxDynamicSharedMemorySize, G1_TOTAL);
    cudaFuncSetAttribute(k_gemm2_mma, cudaFuncAttributeMaxDynamicSharedMemorySize, G2_TOTAL);

    void* p = nullptr;
    cudaGetSymbolAddress(&p, g_cnt);
    cudaMemsetAsync(p, 0, N_NODES * sizeof(int));
    cudaGetSymbolAddress(&p, g_bar);
    cudaMemsetAsync(p, 0, sizeof(int));

    k_csr_a<<<CSR_BLOCKS, 256>>>(dst);                              // 1
    k_pack1<<<(128 * 256 + 255) / 256, 256>>>(W1, Ws02, Ws03);      // 2
    k_pack2<<<(64 * 64 + 255) / 256, 256>>>(W2, Ws13);              // 3
    k_fill<<<N_EDGES / 4 / 256, 256>>>(src, dst);                   // 4 (profiled)
    k_gemm1_mma<<<(N_NODES + 127) / 128, 256, G1_TOTAL>>>(x);       // 5
    k_agg1<<<12500, 256>>>(b1);                                     // 6
    k_gemm2_mma<<<(N_NODES + 127) / 128, 256, G2_TOTAL>>>();        // 7
    k_agg2<<<12500, 256>>>(b2, bs02);                               // 8
    k_gemm3<<<(N_NODES * 16 + 255) / 256, 256>>>(W3);               // 9
    k_agg3<<<12500, 256>>>(b3, bs03, bs13, Wout, bout, out);        // 10
}

// round 14
// speedup vs baseline: 1.4378x; 1.0355x over previous
#include <cuda_runtime.h>
#include <cuda_bf16.h>
#include <cuda_fp16.h>
#include <math.h>
#include <stdint.h>

#define N_NODES 100000
#define N_EDGES 3200000
#define CSR_BLOCKS 512

// ---------------- scratch (static __device__, no allocation) ----------------
__device__ int   g_bar;
__device__ int   g_bsum[CSR_BLOCKS];
__device__ int   g_cnt[N_NODES];
__device__ int   g_rowptr[N_NODES + 1];
__device__ int   g_rank[N_EDGES];      // per-edge within-node rank (from count pass)
__device__ int   g_col[N_EDGES];
__device__ float g_dinv[N_NODES];
__device__ __align__(16) __half g_W1h[128 * 256];   // [n][k] concat W1|Ws02|Ws03 (transposed), fp16
__device__ __align__(16) __half g_W2h[64 * 64];     // [n][k] concat W2|Ws13 (transposed), fp16
__device__ __align__(16) __half g_hs1h[N_NODES * 64];  // fp16: dinv * (x @ W1)
__device__ __align__(16) float  g_s02[N_NODES * 32];   // x @ Ws02
__device__ __align__(16) float  g_s03[N_NODES * 16];   // x @ Ws03
__device__ __align__(16) __half g_x1h[N_NODES * 64];   // fp16 x1
__device__ __align__(16) __half g_hs2h[N_NODES * 32];  // fp16: dinv * (x1 @ W2)
__device__ __align__(16) float  g_s13[N_NODES * 16];   // x1 @ Ws13
__device__ __align__(16) __half g_x2h[N_NODES * 32];   // fp16 x2
__device__ __align__(16) __half g_hs3h[N_NODES * 16];  // fp16: dinv * (x2 @ W3)

// ---------------- helpers ----------------
__device__ __forceinline__ uint32_t smem_u32(const void* p) {
    uint32_t a;
    asm("{ .reg .u64 t; cvta.to.shared.u64 t, %1; cvt.u32.u64 %0, t; }" : "=r"(a) : "l"(p));
    return a;
}

#define SW128(o) ((uint32_t)(o) ^ ((((uint32_t)(o)) >> 3) & 0x70u))

__device__ __forceinline__ void ldsm_x4(uint32_t addr, uint32_t* r) {
    asm volatile("ldmatrix.sync.aligned.m8n8.x4.shared.b16 {%0,%1,%2,%3}, [%4];"
                 : "=r"(r[0]), "=r"(r[1]), "=r"(r[2]), "=r"(r[3]) : "r"(addr));
}

// fp16 x fp16 -> fp32 accumulate
__device__ __forceinline__ void mma16816h(float* c, const uint32_t* a, const uint32_t* b) {
    asm volatile(
        "mma.sync.aligned.m16n8k16.row.col.f32.f16.f16.f32 "
        "{%0,%1,%2,%3}, {%4,%5,%6,%7}, {%8,%9}, {%0,%1,%2,%3};"
        : "+f"(c[0]), "+f"(c[1]), "+f"(c[2]), "+f"(c[3])
        : "r"(a[0]), "r"(a[1]), "r"(a[2]), "r"(a[3]), "r"(b[0]), "r"(b[1]));
}

__device__ __forceinline__ uint32_t pk_h2(__half a, __half b) {
    __half2 t;
    t.x = a; t.y = b;
    return *reinterpret_cast<uint32_t*>(&t);
}

__device__ __forceinline__ void acc_u4(float* f, uint4 v) {
    float2 p;
    p = __half22float2(*reinterpret_cast<__half2*>(&v.x)); f[0] += p.x; f[1] += p.y;
    p = __half22float2(*reinterpret_cast<__half2*>(&v.y)); f[2] += p.x; f[3] += p.y;
    p = __half22float2(*reinterpret_cast<__half2*>(&v.z)); f[4] += p.x; f[5] += p.y;
    p = __half22float2(*reinterpret_cast<__half2*>(&v.w)); f[6] += p.x; f[7] += p.y;
}

// ---------------- CSR phase A (count+rank + scan + dinv/rowptr) ----------------
__device__ __forceinline__ void grid_bar(int target) {
    __syncthreads();
    if (threadIdx.x == 0) {
        __threadfence();
        atomicAdd(&g_bar, 1);
        while (atomicAdd(&g_bar, 0) < target) __nanosleep(64);
        __threadfence();
    }
    __syncthreads();
}

__global__ __launch_bounds__(256, 4) void k_csr_a(const int* __restrict__ dst) {
    const int B = CSR_BLOCKS;
    int tid = threadIdx.x, b = blockIdx.x;
    int gthreads = B * 256;
    int gt = b * 256 + tid;
    __shared__ int sm[256];

    // P1: degree count, persisting each edge's within-node rank
    {
        const int4* dst4 = (const int4*)dst;
        int4* rank4 = (int4*)g_rank;
        const int N4 = N_EDGES / 4;  // 800000
        for (int e = gt; e < N4; e += gthreads) {
            int4 d = dst4[e];
            int4 r;
            r.x = atomicAdd(&g_cnt[d.x], 1);
            r.y = atomicAdd(&g_cnt[d.y], 1);
            r.z = atomicAdd(&g_cnt[d.z], 1);
            r.w = atomicAdd(&g_cnt[d.w], 1);
            rank4[e] = r;
        }
    }
    grid_bar(B);

    // P2a: per-block partial sum over node chunk
    const int CH = (N_NODES + B - 1) / B;          // 196
    int nb = b * CH;
    int ne = nb + CH; if (ne > N_NODES) ne = N_NODES;
    int s = 0;
    for (int i = nb + tid; i < ne; i += 256) s += g_cnt[i];
    sm[tid] = s;
    __syncthreads();
    for (int off = 128; off > 0; off >>= 1) {
        if (tid < off) sm[tid] += sm[tid + off];
        __syncthreads();
    }
    if (tid == 0) g_bsum[b] = sm[0];
    grid_bar(2 * B);

    // P2b: block 0 exclusive-scans the 512 partials
    if (b == 0) {
        int i0 = 2 * tid, i1 = 2 * tid + 1;
        int v0 = (i0 < B) ? g_bsum[i0] : 0;
        int v1 = (i1 < B) ? g_bsum[i1] : 0;
        int tsum = v0 + v1;
        __syncthreads();
        sm[tid] = tsum;
        __syncthreads();
        for (int off = 1; off < 256; off <<= 1) {
            int x = (tid >= off) ? sm[tid - off] : 0;
            __syncthreads();
            sm[tid] += x;
            __syncthreads();
        }
        int run = (tid == 0) ? 0 : sm[tid - 1];
        if (i0 < B) g_bsum[i0] = run;
        run += v0;
        if (i1 < B) g_bsum[i1] = run;
        if (tid == 255) g_rowptr[N_NODES] = sm[255];
    }
    grid_bar(3 * B);

    // P2c: write rowptr/dinv for this block's chunk (CH=196 <= 256)
    {
        int cnt_n = ne - nb;
        int myc = 0;
        if (tid < cnt_n) myc = g_cnt[nb + tid];
        __syncthreads();
        sm[tid] = myc;
        __syncthreads();
        for (int off = 1; off < 256; off <<= 1) {
            int x = (tid >= off) ? sm[tid - off] : 0;
            __syncthreads();
            sm[tid] += x;
            __syncthreads();
        }
        if (tid < cnt_n) {
            int run = g_bsum[b] + ((tid == 0) ? 0 : sm[tid - 1]);
            g_rowptr[nb + tid] = run;
            g_dinv[nb + tid] = rsqrtf((float)myc + 1.0f);
        }
    }
}

// ---------------- CSR fill (atomic-free: rowptr[d] + rank[e]) ----------------
__global__ __launch_bounds__(256) void k_fill(const int* __restrict__ src,
                                              const int* __restrict__ dst) {
    int i = blockIdx.x * 256 + threadIdx.x;     // int4 index; grid exact 3125
    const int4* s4 = (const int4*)src;
    const int4* d4 = (const int4*)dst;
    const int4* r4 = (const int4*)g_rank;
    int4 d = d4[i];
    int4 s = s4[i];
    int4 r = r4[i];
    int p0 = g_rowptr[d.x] + r.x;
    int p1 = g_rowptr[d.y] + r.y;
    int p2 = g_rowptr[d.z] + r.z;
    int p3 = g_rowptr[d.w] + r.w;
    if ((unsigned)p0 < N_EDGES) g_col[p0] = s.x;   // bounds: robustness only
    if ((unsigned)p1 < N_EDGES) g_col[p1] = s.y;
    if ((unsigned)p2 < N_EDGES) g_col[p2] = s.z;
    if ((unsigned)p3 < N_EDGES) g_col[p3] = s.w;
}

// ---------------- weight packing ([n][k] transposed, fp16) ----------------
__global__ void k_pack1(const float* __restrict__ W1, const float* __restrict__ Ws02,
                        const float* __restrict__ Ws03) {
    int i = blockIdx.x * 256 + threadIdx.x;
    if (i >= 128 * 256) return;
    int n = i >> 8, k = i & 255;
    float v = 0.f;
    if (n < 64)       v = W1[k * 64 + n];
    else if (n < 96)  v = Ws02[k * 32 + (n - 64)];
    else if (n < 112) v = Ws03[k * 16 + (n - 96)];
    g_W1h[i] = __float2half(v);
}

__global__ void k_pack2(const float* __restrict__ W2, const float* __restrict__ Ws13) {
    int i = blockIdx.x * 256 + threadIdx.x;
    if (i >= 64 * 64) return;
    int n = i >> 6, k = i & 63;
    float v = 0.f;
    if (n < 32)      v = W2[k * 32 + n];
    else if (n < 48) v = Ws13[k * 16 + (n - 32)];
    g_W2h[i] = __float2half(v);
}

// ---------------- GEMM1 (mma.sync fp16): x[100k,256] @ Wcat1[256,128] ----------------
#define G1_A 0
#define G1_B 16384
#define G1_TOTAL 32768

__global__ __launch_bounds__(256, 2) void k_gemm1_mma(const float* __restrict__ X) {
    extern __shared__ __align__(1024) char smem[];
    uint32_t sb = smem_u32(smem);
    int tid = threadIdx.x, wid = tid >> 5, lane = tid & 31;
    int rowBase = blockIdx.x * 128;
    int mw = wid >> 1, nw = wid & 1;          // 4 m-warps x 2 n-warps
    int g = lane >> 2, t4 = lane & 3;

    float c[2][8][4];
    #pragma unroll
    for (int a = 0; a < 2; a++)
        #pragma unroll
        for (int b = 0; b < 8; b++)
            #pragma unroll
            for (int d = 0; d < 4; d++) c[a][b][d] = 0.f;

    int lr = lane & 7, lts = lane >> 3;
    int aRow = tid >> 4, aKq = (tid & 15) * 4;

    for (int ch = 0; ch < 4; ch++) {
        int kt = ch * 64;
        float4 v[8];
        #pragma unroll
        for (int i = 0; i < 8; i++) {
            int row = aRow + i * 16;
            int gr = rowBase + row;
            v[i] = (gr < N_NODES) ? *(const float4*)(X + (size_t)gr * 256 + kt + aKq)
                                  : make_float4(0.f, 0.f, 0.f, 0.f);
        }
        __syncthreads();
        #pragma unroll
        for (int i = 0; i < 8; i++) {
            int row = aRow + i * 16;
            uint32_t p0 = pk_h2(__float2half(v[i].x), __float2half(v[i].y));
            uint32_t p1 = pk_h2(__float2half(v[i].z), __float2half(v[i].w));
            uint32_t off = SW128(row * 128 + aKq * 2);
            *(uint2*)(smem + G1_A + off) = make_uint2(p0, p1);
        }
        #pragma unroll
        for (int i = 0; i < 4; i++) {
            int gidx = tid + i * 256;               // 0..1023
            int n = gidx >> 3, q = gidx & 7;
            uint32_t off = SW128(n * 128 + q * 16);
            size_t gb = (size_t)n * 512 + (size_t)(kt + q * 8) * 2;
            *(uint4*)(smem + G1_B + off) = *(const uint4*)((const char*)g_W1h + gb);
        }
        __syncthreads();

        #pragma unroll
        for (int ks = 0; ks < 4; ks++) {
            int k0 = ks * 16;
            uint32_t aF[2][4];
            #pragma unroll
            for (int mt = 0; mt < 2; mt++) {
                int row = mw * 32 + mt * 16 + lr + ((lts & 1) << 3);
                int kk = k0 + ((lts >> 1) << 3);
                uint32_t off = SW128(row * 128 + kk * 2);
                ldsm_x4(sb + G1_A + off, aF[mt]);
            }
            #pragma unroll
            for (int q = 0; q < 2; q++) {
                int n = nw * 64 + (q * 4 + lts) * 8 + lr;
                uint32_t offLo = SW128(n * 128 + k0 * 2);
                uint32_t offHi = SW128(n * 128 + (k0 + 8) * 2);
                uint32_t t0[4], t1[4];
                ldsm_x4(sb + G1_B + offLo, t0);
                ldsm_x4(sb + G1_B + offHi, t1);
                #pragma unroll
                for (int j = 0; j < 4; j++) {
                    uint32_t bf[2] = { t0[j], t1[j] };
                    #pragma unroll
                    for (int mt = 0; mt < 2; mt++)
                        mma16816h(c[mt][q * 4 + j], aF[mt], bf);
                }
            }
        }
    }

    // epilogue: hs1 fp16, s02/s03 fp32
    #pragma unroll
    for (int mt = 0; mt < 2; mt++) {
        int r0 = rowBase + mw * 32 + mt * 16 + g;
        int r1 = r0 + 8;
        float dv0 = (r0 < N_NODES) ? g_dinv[r0] : 0.f;
        float dv1 = (r1 < N_NODES) ? g_dinv[r1] : 0.f;
        #pragma unroll
        for (int j = 0; j < 8; j++) {
            int col = nw * 64 + j * 8 + t4 * 2;
            float c0 = c[mt][j][0], c1 = c[mt][j][1];
            float c2 = c[mt][j][2], c3 = c[mt][j][3];
            if (r0 < N_NODES) {
                if (col < 64) {
                    *(__half2*)(g_hs1h + (size_t)r0 * 64 + col) = __floats2half2_rn(dv0 * c0, dv0 * c1);
                } else if (col < 96)  *(float2*)(g_s02 + (size_t)r0 * 32 + (col - 64)) = make_float2(c0, c1);
                else if (col < 112)   *(float2*)(g_s03 + (size_t)r0 * 16 + (col - 96)) = make_float2(c0, c1);
            }
            if (r1 < N_NODES) {
                if (col < 64) {
                    *(__half2*)(g_hs1h + (size_t)r1 * 64 + col) = __floats2half2_rn(dv1 * c2, dv1 * c3);
                } else if (col < 96)  *(float2*)(g_s02 + (size_t)r1 * 32 + (col - 64)) = make_float2(c2, c3);
                else if (col < 112)   *(float2*)(g_s03 + (size_t)r1 * 16 + (col - 96)) = make_float2(c2, c3);
            }
        }
    }
}

// ---------------- GEMM2 (mma.sync fp16): x1[100k,64] @ Wcat2[64,64] ----------------
#define G2_A 0
#define G2_B 16384
#define G2_TOTAL 24576

__global__ __launch_bounds__(256, 2) void k_gemm2_mma() {
    extern __shared__ __align__(1024) char smem[];
    uint32_t sb = smem_u32(smem);
    int tid = threadIdx.x, wid = tid >> 5, lane = tid & 31;
    int rowBase = blockIdx.x * 128;
    int mw = wid >> 1, nw = wid & 1;
    int g = lane >> 2, t4 = lane & 3;
    int lr = lane & 7, lts = lane >> 3;

    float c[2][4][4];
    #pragma unroll
    for (int a = 0; a < 2; a++)
        #pragma unroll
        for (int b = 0; b < 4; b++)
            #pragma unroll
            for (int d = 0; d < 4; d++) c[a][b][d] = 0.f;

    #pragma unroll
    for (int i = 0; i < 4; i++) {
        int gidx = tid + i * 256;
        int row = gidx >> 3, q = gidx & 7;
        int gr = rowBase + row;
        uint32_t off = SW128(row * 128 + q * 16);
        if (gr < N_NODES) {
            *(uint4*)(smem + G2_A + off) = *(const uint4*)((const char*)g_x1h + (size_t)gr * 128 + (size_t)q * 16);
        } else {
            *(uint4*)(smem + G2_A + off) = make_uint4(0, 0, 0, 0);
        }
    }
    #pragma unroll
    for (int i = 0; i < 2; i++) {
        int gidx = tid + i * 256;
        int n = gidx >> 3, q = gidx & 7;
        uint32_t off = SW128(n * 128 + q * 16);
        *(uint4*)(smem + G2_B + off) = *(const uint4*)((const char*)g_W2h + (size_t)n * 128 + (size_t)q * 16);
    }
    __syncthreads();

    #pragma unroll
    for (int ks = 0; ks < 4; ks++) {
        int k0 = ks * 16;
        uint32_t aF[2][4], bF[4][2];
        #pragma unroll
        for (int mt = 0; mt < 2; mt++) {
            int row = mw * 32 + mt * 16 + lr + ((lts & 1) << 3);
            int kk = k0 + ((lts >> 1) << 3);
            uint32_t off = SW128(row * 128 + kk * 2);
            ldsm_x4(sb + G2_A + off, aF[mt]);
        }
        {
            int n = nw * 32 + lts * 8 + lr;
            uint32_t offLo = SW128(n * 128 + k0 * 2);
            uint32_t offHi = SW128(n * 128 + (k0 + 8) * 2);
            uint32_t t0[4], t1[4];
            ldsm_x4(sb + G2_B + offLo, t0);
            ldsm_x4(sb + G2_B + offHi, t1);
            #pragma unroll
            for (int j = 0; j < 4; j++) { bF[j][0] = t0[j]; bF[j][1] = t1[j]; }
        }
        #pragma unroll
        for (int mt = 0; mt < 2; mt++)
            #pragma unroll
            for (int j = 0; j < 4; j++)
                mma16816h(c[mt][j], aF[mt], bF[j]);
    }

    #pragma unroll
    for (int mt = 0; mt < 2; mt++) {
        int r0 = rowBase + mw * 32 + mt * 16 + g;
        int r1 = r0 + 8;
        float dv0 = (r0 < N_NODES) ? g_dinv[r0] : 0.f;
        float dv1 = (r1 < N_NODES) ? g_dinv[r1] : 0.f;
        #pragma unroll
        for (int j = 0; j < 4; j++) {
            int col = nw * 32 + j * 8 + t4 * 2;
            float c0 = c[mt][j][0], c1 = c[mt][j][1];
            float c2 = c[mt][j][2], c3 = c[mt][j][3];
            if (r0 < N_NODES) {
                if (col < 32) {
                    *(__half2*)(g_hs2h + (size_t)r0 * 32 + col) = __floats2half2_rn(dv0 * c0, dv0 * c1);
                } else if (col < 48) *(float2*)(g_s13 + (size_t)r0 * 16 + (col - 32)) = make_float2(c0, c1);
            }
            if (r1 < N_NODES) {
                if (col < 32) {
                    *(__half2*)(g_hs2h + (size_t)r1 * 32 + col) = __floats2half2_rn(dv1 * c2, dv1 * c3);
                } else if (col < 48) *(float2*)(g_s13 + (size_t)r1 * 16 + (col - 32)) = make_float2(c2, c3);
            }
        }
    }
}

// ---------------- GEMM 3 (small): x2[100k,32] @ W3[32,16] ----------------
__global__ __launch_bounds__(256) void k_gemm3(const float* __restrict__ W3) {
    __shared__ float sW[32 * 16];
    int tid = threadIdx.x;
    sW[tid] = W3[tid];
    sW[tid + 256] = W3[tid + 256];
    __syncthreads();
    int gid = blockIdx.x * 256 + tid;
    int node = gid >> 4, cc = gid & 15;
    const __half2* xr = (const __half2*)(g_x2h + (size_t)node * 32);
    float acc = 0.f;
    #pragma unroll
    for (int k = 0; k < 16; k++) {
        float2 p = __half22float2(xr[k]);
        acc += p.x * sW[(2 * k) * 16 + cc] + p.y * sW[(2 * k + 1) * 16 + cc];
    }
    g_hs3h[gid] = __float2half(g_dinv[node] * acc);
}

// ---------------- shfl-free warp-cooperative CSR aggregation (fp16 rows) ----------------
// agg1: DIM=64 fp16 -> 8 uint4/row. 4 groups of 8 lanes; each group walks every 4th edge.
__global__ __launch_bounds__(256) void k_agg1(const float* __restrict__ b1) {
    int wid = threadIdx.x >> 5, lane = threadIdx.x & 31;
    int node = blockIdx.x * 8 + wid;
    int oc = lane >> 3, fl = lane & 7;
    const uint4* hs = (const uint4*)g_hs1h;
    int beg = g_rowptr[node], end = g_rowptr[node + 1];
    float f[8] = {0.f, 0.f, 0.f, 0.f, 0.f, 0.f, 0.f, 0.f};
    if (oc == 0) acc_u4(f, hs[(size_t)node * 8 + fl]);   // self term (prescaled)
    int e = beg + oc;
    for (; e + 4 < end; e += 8) {
        int j0 = g_col[e];
        int j1 = g_col[e + 4];
        acc_u4(f, hs[(size_t)j0 * 8 + fl]);
        acc_u4(f, hs[(size_t)j1 * 8 + fl]);
    }
    if (e < end) acc_u4(f, hs[(size_t)g_col[e] * 8 + fl]);
    #pragma unroll
    for (int i = 0; i < 8; i++) {
        f[i] += __shfl_xor_sync(0xffffffffu, f[i], 8);
        f[i] += __shfl_xor_sync(0xffffffffu, f[i], 16);
    }
    if (oc == 0) {
        float dv = g_dinv[node];
        float4 b0 = ((const float4*)b1)[2 * fl];
        float4 b4 = ((const float4*)b1)[2 * fl + 1];
        float o[8];
        o[0] = fmaxf(dv * f[0] + b0.x, 0.f); o[1] = fmaxf(dv * f[1] + b0.y, 0.f);
        o[2] = fmaxf(dv * f[2] + b0.z, 0.f); o[3] = fmaxf(dv * f[3] + b0.w, 0.f);
        o[4] = fmaxf(dv * f[4] + b4.x, 0.f); o[5] = fmaxf(dv * f[5] + b4.y, 0.f);
        o[6] = fmaxf(dv * f[6] + b4.z, 0.f); o[7] = fmaxf(dv * f[7] + b4.w, 0.f);
        uint4 hv;
        uint32_t* hp = (uint32_t*)&hv;
        #pragma unroll
        for (int q = 0; q < 4; q++) {
            __half2 p = __floats2half2_rn(o[2 * q], o[2 * q + 1]);
            hp[q] = *reinterpret_cast<uint32_t*>(&p);
        }
        ((uint4*)g_x1h)[(size_t)node * 8 + fl] = hv;
    }
}

// agg2: DIM=32 fp16 -> 4 uint4/row. 8 groups of 4 lanes, stride 8.
__global__ __launch_bounds__(256) void k_agg2(const float* __restrict__ b2,
                                              const float* __restrict__ bs02) {
    int wid = threadIdx.x >> 5, lane = threadIdx.x & 31;
    int node = blockIdx.x * 8 + wid;
    int oc = lane >> 2, fl = lane & 3;
    const uint4* hs = (const uint4*)g_hs2h;
    int beg = g_rowptr[node], end = g_rowptr[node + 1];
    float f[8] = {0.f, 0.f, 0.f, 0.f, 0.f, 0.f, 0.f, 0.f};
    if (oc == 0) acc_u4(f, hs[(size_t)node * 4 + fl]);
    int e = beg + oc;
    for (; e + 8 < end; e += 16) {
        int j0 = g_col[e];
        int j1 = g_col[e + 8];
        acc_u4(f, hs[(size_t)j0 * 4 + fl]);
        acc_u4(f, hs[(size_t)j1 * 4 + fl]);
    }
    if (e < end) acc_u4(f, hs[(size_t)g_col[e] * 4 + fl]);
    #pragma unroll
    for (int i = 0; i < 8; i++) {
        f[i] += __shfl_xor_sync(0xffffffffu, f[i], 4);
        f[i] += __shfl_xor_sync(0xffffffffu, f[i], 8);
        f[i] += __shfl_xor_sync(0xffffffffu, f[i], 16);
    }
    if (oc == 0) {
        float dv = g_dinv[node];
        float4 b0 = ((const float4*)b2)[2 * fl];
        float4 b4 = ((const float4*)b2)[2 * fl + 1];
        float4 sb0 = ((const float4*)bs02)[2 * fl];
        float4 sb4 = ((const float4*)bs02)[2 * fl + 1];
        float4 s0 = ((const float4*)g_s02)[(size_t)node * 8 + 2 * fl];
        float4 s4 = ((const float4*)g_s02)[(size_t)node * 8 + 2 * fl + 1];
        float o[8];
        o[0] = fmaxf(dv * f[0] + b0.x + s0.x + sb0.x, 0.f);
        o[1] = fmaxf(dv * f[1] + b0.y + s0.y + sb0.y, 0.f);
        o[2] = fmaxf(dv * f[2] + b0.z + s0.z + sb0.z, 0.f);
        o[3] = fmaxf(dv * f[3] + b0.w + s0.w + sb0.w, 0.f);
        o[4] = fmaxf(dv * f[4] + b4.x + s4.x + sb4.x, 0.f);
        o[5] = fmaxf(dv * f[5] + b4.y + s4.y + sb4.y, 0.f);
        o[6] = fmaxf(dv * f[6] + b4.z + s4.z + sb4.z, 0.f);
        o[7] = fmaxf(dv * f[7] + b4.w + s4.w + sb4.w, 0.f);
        uint4 hv;
        uint32_t* hp = (uint32_t*)&hv;
        #pragma unroll
        for (int q = 0; q < 4; q++) {
            __half2 p = __floats2half2_rn(o[2 * q], o[2 * q + 1]);
            hp[q] = *reinterpret_cast<uint32_t*>(&p);
        }
        ((uint4*)g_x2h)[(size_t)node * 4 + fl] = hv;
    }
}

// agg3: DIM=16 fp16 -> 2 uint4/row. 16 groups of 2 lanes, stride 16. Fused head.
__global__ __launch_bounds__(256) void k_agg3(const float* __restrict__ b3,
                                              const float* __restrict__ bs03,
                                              const float* __restrict__ bs13,
                                              const float* __restrict__ Wout,
                                              const float* __restrict__ bout,
                                              float* __restrict__ out) {
    int wid = threadIdx.x >> 5, lane = threadIdx.x & 31;
    int node = blockIdx.x * 8 + wid;
    int oc = lane >> 1, fl = lane & 1;
    const uint4* hs = (const uint4*)g_hs3h;
    int beg = g_rowptr[node], end = g_rowptr[node + 1];
    float f[8] = {0.f, 0.f, 0.f, 0.f, 0.f, 0.f, 0.f, 0.f};
    if (oc == 0) acc_u4(f, hs[(size_t)node * 2 + fl]);
    int e = beg + oc;
    for (; e + 16 < end; e += 32) {
        int j0 = g_col[e];
        int j1 = g_col[e + 16];
        acc_u4(f, hs[(size_t)j0 * 2 + fl]);
        acc_u4(f, hs[(size_t)j1 * 2 + fl]);
    }
    if (e < end) acc_u4(f, hs[(size_t)g_col[e] * 2 + fl]);
    #pragma unroll
    for (int i = 0; i < 8; i++) {
        f[i] += __shfl_xor_sync(0xffffffffu, f[i], 2);
        f[i] += __shfl_xor_sync(0xffffffffu, f[i], 4);
        f[i] += __shfl_xor_sync(0xffffffffu, f[i], 8);
        f[i] += __shfl_xor_sync(0xffffffffu, f[i], 16);
    }
    float dv = g_dinv[node];
    float4 b0 = ((const float4*)b3)[2 * fl];
    float4 b4 = ((const float4*)b3)[2 * fl + 1];
    float4 q0 = ((const float4*)bs03)[2 * fl];
    float4 q4 = ((const float4*)bs03)[2 * fl + 1];
    float4 r0 = ((const float4*)bs13)[2 * fl];
    float4 r4 = ((const float4*)bs13)[2 * fl + 1];
    float4 s0 = ((const float4*)g_s03)[(size_t)node * 4 + 2 * fl];
    float4 s4 = ((const float4*)g_s03)[(size_t)node * 4 + 2 * fl + 1];
    float4 u0 = ((const float4*)g_s13)[(size_t)node * 4 + 2 * fl];
    float4 u4 = ((const float4*)g_s13)[(size_t)node * 4 + 2 * fl + 1];
    float4 w0 = ((const float4*)Wout)[2 * fl];
    float4 w4 = ((const float4*)Wout)[2 * fl + 1];
    float t0 = fmaxf(dv * f[0] + b0.x + s0.x + q0.x + u0.x + r0.x, 0.f);
    float t1 = fmaxf(dv * f[1] + b0.y + s0.y + q0.y + u0.y + r0.y, 0.f);
    float t2 = fmaxf(dv * f[2] + b0.z + s0.z + q0.z + u0.z + r0.z, 0.f);
    float t3 = fmaxf(dv * f[3] + b0.w + s0.w + q0.w + u0.w + r0.w, 0.f);
    float t4v = fmaxf(dv * f[4] + b4.x + s4.x + q4.x + u4.x + r4.x, 0.f);
    float t5 = fmaxf(dv * f[5] + b4.y + s4.y + q4.y + u4.y + r4.y, 0.f);
    float t6 = fmaxf(dv * f[6] + b4.z + s4.z + q4.z + u4.z + r4.z, 0.f);
    float t7 = fmaxf(dv * f[7] + b4.w + s4.w + q4.w + u4.w + r4.w, 0.f);
    float v = t0 * w0.x + t1 * w0.y + t2 * w0.z + t3 * w0.w
            + t4v * w4.x + t5 * w4.y + t6 * w4.z + t7 * w4.w;
    v += __shfl_xor_sync(0xffffffffu, v, 1);
    if (lane == 0) out[node] = 1.f / (1.f + __expf(-(v + bout[0])));
}

// ---------------- launch ----------------
extern "C" void kernel_launch(void* const* d_in, const int* in_sizes, int n_in,
                              void* d_out, int out_size) {
    const float* x    = (const float*)d_in[0];
    const int*   ei   = (const int*)d_in[1];
    const float* W1   = (const float*)d_in[2];
    const float* b1   = (const float*)d_in[3];
    const float* W2   = (const float*)d_in[4];
    const float* b2   = (const float*)d_in[5];
    const float* W3   = (const float*)d_in[6];
    const float* b3   = (const float*)d_in[7];
    const float* Ws02 = (const float*)d_in[8];
    const float* bs02 = (const float*)d_in[9];
    const float* Ws03 = (const float*)d_in[10];
    const float* bs03 = (const float*)d_in[11];
    const float* Ws13 = (const float*)d_in[12];
    const float* bs13 = (const float*)d_in[13];
    const float* Wout = (const float*)d_in[14];
    const float* bout = (const float*)d_in[15];
    float* out = (float*)d_out;

    const int* src = ei;
    const int* dst = ei + N_EDGES;

    cudaFuncSetAttribute(k_gemm1_mma, cudaFuncAttributeMaxDynamicSharedMemorySize, G1_TOTAL);
    cudaFuncSetAttribute(k_gemm2_mma, cudaFuncAttributeMaxDynamicSharedMemorySize, G2_TOTAL);

    void* p = nullptr;
    cudaGetSymbolAddress(&p, g_cnt);
    cudaMemsetAsync(p, 0, N_NODES * sizeof(int));
    cudaGetSymbolAddress(&p, g_bar);
    cudaMemsetAsync(p, 0, sizeof(int));

    k_csr_a<<<CSR_BLOCKS, 256>>>(dst);                              // 1
    k_pack1<<<(128 * 256 + 255) / 256, 256>>>(W1, Ws02, Ws03);      // 2
    k_pack2<<<(64 * 64 + 255) / 256, 256>>>(W2, Ws13);              // 3
    k_fill<<<N_EDGES / 4 / 256, 256>>>(src, dst);                   // 4 (profiled)
    k_gemm1_mma<<<(N_NODES + 127) / 128, 256, G1_TOTAL>>>(x);       // 5
    k_agg1<<<12500, 256>>>(b1);                                     // 6
    k_gemm2_mma<<<(N_NODES + 127) / 128, 256, G2_TOTAL>>>();        // 7
    k_agg2<<<12500, 256>>>(b2, bs02);                               // 8
    k_gemm3<<<(N_NODES * 16 + 255) / 256, 256>>>(W3);               // 9
    k_agg3<<<12500, 256>>>(b3, bs03, bs13, Wout, bout, out);        // 10
}

// round 15
// speedup vs baseline: 1.5033x; 1.0456x over previous
#include <cuda_runtime.h>
#include <cuda_bf16.h>
#include <cuda_fp16.h>
#include <math.h>
#include <stdint.h>

#define N_NODES 100000
#define N_EDGES 3200000
#define CSR_BLOCKS 512

// ---------------- scratch (static __device__, no allocation) ----------------
__device__ int   g_bar;
__device__ int   g_bsum[CSR_BLOCKS];
__device__ int   g_cnt[N_NODES];
__device__ int   g_rowptr[N_NODES + 1];
__device__ int   g_rank[N_EDGES];      // per-edge within-node rank (from count pass)
__device__ int   g_col[N_EDGES];
__device__ float g_dinv[N_NODES];
__device__ __align__(16) __half g_W1h[128 * 256];   // [n][k] concat W1|Ws02|Ws03 (transposed), fp16
__device__ __align__(16) __half g_W2h[64 * 64];     // [n][k] concat W2|Ws13 (transposed), fp16
__device__ __align__(16) __half g_hs1h[N_NODES * 64];  // fp16: dinv * (x @ W1)
__device__ __align__(16) float  g_s02[N_NODES * 32];   // x @ Ws02
__device__ __align__(16) float  g_s03[N_NODES * 16];   // x @ Ws03
__device__ __align__(16) __half g_x1h[N_NODES * 64];   // fp16 x1
__device__ __align__(16) __half g_hs2h[N_NODES * 32];  // fp16: dinv * (x1 @ W2)
__device__ __align__(16) float  g_s13[N_NODES * 16];   // x1 @ Ws13
__device__ __align__(16) __half g_x2h[N_NODES * 32];   // fp16 x2
__device__ __align__(16) __half g_hs3h[N_NODES * 16];  // fp16: dinv * (x2 @ W3)

// ---------------- helpers ----------------
__device__ __forceinline__ uint32_t smem_u32(const void* p) {
    uint32_t a;
    asm("{ .reg .u64 t; cvta.to.shared.u64 t, %1; cvt.u32.u64 %0, t; }" : "=r"(a) : "l"(p));
    return a;
}

#define SW128(o) ((uint32_t)(o) ^ ((((uint32_t)(o)) >> 3) & 0x70u))

__device__ __forceinline__ void ldsm_x4(uint32_t addr, uint32_t* r) {
    asm volatile("ldmatrix.sync.aligned.m8n8.x4.shared.b16 {%0,%1,%2,%3}, [%4];"
                 : "=r"(r[0]), "=r"(r[1]), "=r"(r[2]), "=r"(r[3]) : "r"(addr));
}

// fp16 x fp16 -> fp32 accumulate
__device__ __forceinline__ void mma16816h(float* c, const uint32_t* a, const uint32_t* b) {
    asm volatile(
        "mma.sync.aligned.m16n8k16.row.col.f32.f16.f16.f32 "
        "{%0,%1,%2,%3}, {%4,%5,%6,%7}, {%8,%9}, {%0,%1,%2,%3};"
        : "+f"(c[0]), "+f"(c[1]), "+f"(c[2]), "+f"(c[3])
        : "r"(a[0]), "r"(a[1]), "r"(a[2]), "r"(a[3]), "r"(b[0]), "r"(b[1]));
}

__device__ __forceinline__ uint32_t pk_h2(__half a, __half b) {
    __half2 t;
    t.x = a; t.y = b;
    return *reinterpret_cast<uint32_t*>(&t);
}

__device__ __forceinline__ void acc_u4(float* f, uint4 v) {
    float2 p;
    p = __half22float2(*reinterpret_cast<__half2*>(&v.x)); f[0] += p.x; f[1] += p.y;
    p = __half22float2(*reinterpret_cast<__half2*>(&v.y)); f[2] += p.x; f[3] += p.y;
    p = __half22float2(*reinterpret_cast<__half2*>(&v.z)); f[4] += p.x; f[5] += p.y;
    p = __half22float2(*reinterpret_cast<__half2*>(&v.w)); f[6] += p.x; f[7] += p.y;
}

// 4x HADD2: combine two fp16 rows (single rounding per pair; err ~eps16/pair)
__device__ __forceinline__ uint4 hadd2_u4(uint4 a, uint4 b) {
    uint4 r;
    *(__half2*)&r.x = __hadd2(*(__half2*)&a.x, *(__half2*)&b.x);
    *(__half2*)&r.y = __hadd2(*(__half2*)&a.y, *(__half2*)&b.y);
    *(__half2*)&r.z = __hadd2(*(__half2*)&a.z, *(__half2*)&b.z);
    *(__half2*)&r.w = __hadd2(*(__half2*)&a.w, *(__half2*)&b.w);
    return r;
}

// ---------------- CSR phase A (count+rank + scan + dinv/rowptr) ----------------
__device__ __forceinline__ void grid_bar(int target) {
    __syncthreads();
    if (threadIdx.x == 0) {
        __threadfence();
        atomicAdd(&g_bar, 1);
        while (atomicAdd(&g_bar, 0) < target) __nanosleep(64);
        __threadfence();
    }
    __syncthreads();
}

__global__ __launch_bounds__(256, 4) void k_csr_a(const int* __restrict__ dst) {
    const int B = CSR_BLOCKS;
    int tid = threadIdx.x, b = blockIdx.x;
    int gthreads = B * 256;
    int gt = b * 256 + tid;
    __shared__ int sm[256];

    // P1: degree count, persisting each edge's within-node rank
    {
        const int4* dst4 = (const int4*)dst;
        int4* rank4 = (int4*)g_rank;
        const int N4 = N_EDGES / 4;  // 800000
        for (int e = gt; e < N4; e += gthreads) {
            int4 d = dst4[e];
            int4 r;
            r.x = atomicAdd(&g_cnt[d.x], 1);
            r.y = atomicAdd(&g_cnt[d.y], 1);
            r.z = atomicAdd(&g_cnt[d.z], 1);
            r.w = atomicAdd(&g_cnt[d.w], 1);
            rank4[e] = r;
        }
    }
    grid_bar(B);

    // P2a: per-block partial sum over node chunk
    const int CH = (N_NODES + B - 1) / B;          // 196
    int nb = b * CH;
    int ne = nb + CH; if (ne > N_NODES) ne = N_NODES;
    int s = 0;
    for (int i = nb + tid; i < ne; i += 256) s += g_cnt[i];
    sm[tid] = s;
    __syncthreads();
    for (int off = 128; off > 0; off >>= 1) {
        if (tid < off) sm[tid] += sm[tid + off];
        __syncthreads();
    }
    if (tid == 0) g_bsum[b] = sm[0];
    grid_bar(2 * B);

    // P2b: block 0 exclusive-scans the 512 partials
    if (b == 0) {
        int i0 = 2 * tid, i1 = 2 * tid + 1;
        int v0 = (i0 < B) ? g_bsum[i0] : 0;
        int v1 = (i1 < B) ? g_bsum[i1] : 0;
        int tsum = v0 + v1;
        __syncthreads();
        sm[tid] = tsum;
        __syncthreads();
        for (int off = 1; off < 256; off <<= 1) {
            int x = (tid >= off) ? sm[tid - off] : 0;
            __syncthreads();
            sm[tid] += x;
            __syncthreads();
        }
        int run = (tid == 0) ? 0 : sm[tid - 1];
        if (i0 < B) g_bsum[i0] = run;
        run += v0;
        if (i1 < B) g_bsum[i1] = run;
        if (tid == 255) g_rowptr[N_NODES] = sm[255];
    }
    grid_bar(3 * B);

    // P2c: write rowptr/dinv for this block's chunk (CH=196 <= 256)
    {
        int cnt_n = ne - nb;
        int myc = 0;
        if (tid < cnt_n) myc = g_cnt[nb + tid];
        __syncthreads();
        sm[tid] = myc;
        __syncthreads();
        for (int off = 1; off < 256; off <<= 1) {
            int x = (tid >= off) ? sm[tid - off] : 0;
            __syncthreads();
            sm[tid] += x;
            __syncthreads();
        }
        if (tid < cnt_n) {
            int run = g_bsum[b] + ((tid == 0) ? 0 : sm[tid - 1]);
            g_rowptr[nb + tid] = run;
            g_dinv[nb + tid] = rsqrtf((float)myc + 1.0f);
        }
    }
}

// ---------------- CSR fill (atomic-free: rowptr[d] + rank[e]) ----------------
__global__ __launch_bounds__(256) void k_fill(const int* __restrict__ src,
                                              const int* __restrict__ dst) {
    int i = blockIdx.x * 256 + threadIdx.x;     // int4 index; grid exact 3125
    const int4* s4 = (const int4*)src;
    const int4* d4 = (const int4*)dst;
    const int4* r4 = (const int4*)g_rank;
    int4 d = d4[i];
    int4 s = s4[i];
    int4 r = r4[i];
    int p0 = g_rowptr[d.x] + r.x;
    int p1 = g_rowptr[d.y] + r.y;
    int p2 = g_rowptr[d.z] + r.z;
    int p3 = g_rowptr[d.w] + r.w;
    if ((unsigned)p0 < N_EDGES) g_col[p0] = s.x;   // bounds: robustness only
    if ((unsigned)p1 < N_EDGES) g_col[p1] = s.y;
    if ((unsigned)p2 < N_EDGES) g_col[p2] = s.z;
    if ((unsigned)p3 < N_EDGES) g_col[p3] = s.w;
}

// ---------------- weight packing (merged pack1+pack2, fp16 [n][k]) ----------------
__global__ void k_packs(const float* __restrict__ W1, const float* __restrict__ Ws02,
                        const float* __restrict__ Ws03, const float* __restrict__ W2,
                        const float* __restrict__ Ws13) {
    int i = blockIdx.x * 256 + threadIdx.x;
    if (i < 128 * 256) {
        int n = i >> 8, k = i & 255;
        float v = 0.f;
        if (n < 64)       v = W1[k * 64 + n];
        else if (n < 96)  v = Ws02[k * 32 + (n - 64)];
        else if (n < 112) v = Ws03[k * 16 + (n - 96)];
        g_W1h[i] = __float2half(v);
    } else if (i < 128 * 256 + 64 * 64) {
        int j = i - 128 * 256;
        int n = j >> 6, k = j & 63;
        float v = 0.f;
        if (n < 32)      v = W2[k * 32 + n];
        else if (n < 48) v = Ws13[k * 16 + (n - 32)];
        g_W2h[j] = __float2half(v);
    }
}

// ---------------- GEMM1 (mma.sync fp16): x[100k,256] @ Wcat1[256,128] ----------------
#define G1_A 0
#define G1_B 16384
#define G1_TOTAL 32768

__global__ __launch_bounds__(256, 2) void k_gemm1_mma(const float* __restrict__ X) {
    extern __shared__ __align__(1024) char smem[];
    uint32_t sb = smem_u32(smem);
    int tid = threadIdx.x, wid = tid >> 5, lane = tid & 31;
    int rowBase = blockIdx.x * 128;
    int mw = wid >> 1, nw = wid & 1;          // 4 m-warps x 2 n-warps
    int g = lane >> 2, t4 = lane & 3;

    float c[2][8][4];
    #pragma unroll
    for (int a = 0; a < 2; a++)
        #pragma unroll
        for (int b = 0; b < 8; b++)
            #pragma unroll
            for (int d = 0; d < 4; d++) c[a][b][d] = 0.f;

    int lr = lane & 7, lts = lane >> 3;
    int aRow = tid >> 4, aKq = (tid & 15) * 4;

    for (int ch = 0; ch < 4; ch++) {
        int kt = ch * 64;
        float4 v[8];
        #pragma unroll
        for (int i = 0; i < 8; i++) {
            int row = aRow + i * 16;
            int gr = rowBase + row;
            v[i] = (gr < N_NODES) ? *(const float4*)(X + (size_t)gr * 256 + kt + aKq)
                                  : make_float4(0.f, 0.f, 0.f, 0.f);
        }
        __syncthreads();
        #pragma unroll
        for (int i = 0; i < 8; i++) {
            int row = aRow + i * 16;
            uint32_t p0 = pk_h2(__float2half(v[i].x), __float2half(v[i].y));
            uint32_t p1 = pk_h2(__float2half(v[i].z), __float2half(v[i].w));
            uint32_t off = SW128(row * 128 + aKq * 2);
            *(uint2*)(smem + G1_A + off) = make_uint2(p0, p1);
        }
        #pragma unroll
        for (int i = 0; i < 4; i++) {
            int gidx = tid + i * 256;               // 0..1023
            int n = gidx >> 3, q = gidx & 7;
            uint32_t off = SW128(n * 128 + q * 16);
            size_t gb = (size_t)n * 512 + (size_t)(kt + q * 8) * 2;
            *(uint4*)(smem + G1_B + off) = *(const uint4*)((const char*)g_W1h + gb);
        }
        __syncthreads();

        #pragma unroll
        for (int ks = 0; ks < 4; ks++) {
            int k0 = ks * 16;
            uint32_t aF[2][4];
            #pragma unroll
            for (int mt = 0; mt < 2; mt++) {
                int row = mw * 32 + mt * 16 + lr + ((lts & 1) << 3);
                int kk = k0 + ((lts >> 1) << 3);
                uint32_t off = SW128(row * 128 + kk * 2);
                ldsm_x4(sb + G1_A + off, aF[mt]);
            }
            #pragma unroll
            for (int q = 0; q < 2; q++) {
                int n = nw * 64 + (q * 4 + lts) * 8 + lr;
                uint32_t offLo = SW128(n * 128 + k0 * 2);
                uint32_t offHi = SW128(n * 128 + (k0 + 8) * 2);
                uint32_t t0[4], t1[4];
                ldsm_x4(sb + G1_B + offLo, t0);
                ldsm_x4(sb + G1_B + offHi, t1);
                #pragma unroll
                for (int j = 0; j < 4; j++) {
                    uint32_t bf[2] = { t0[j], t1[j] };
                    #pragma unroll
                    for (int mt = 0; mt < 2; mt++)
                        mma16816h(c[mt][q * 4 + j], aF[mt], bf);
                }
            }
        }
    }

    // epilogue: hs1 fp16, s02/s03 fp32
    #pragma unroll
    for (int mt = 0; mt < 2; mt++) {
        int r0 = rowBase + mw * 32 + mt * 16 + g;
        int r1 = r0 + 8;
        float dv0 = (r0 < N_NODES) ? g_dinv[r0] : 0.f;
        float dv1 = (r1 < N_NODES) ? g_dinv[r1] : 0.f;
        #pragma unroll
        for (int j = 0; j < 8; j++) {
            int col = nw * 64 + j * 8 + t4 * 2;
            float c0 = c[mt][j][0], c1 = c[mt][j][1];
            float c2 = c[mt][j][2], c3 = c[mt][j][3];
            if (r0 < N_NODES) {
                if (col < 64) {
                    *(__half2*)(g_hs1h + (size_t)r0 * 64 + col) = __floats2half2_rn(dv0 * c0, dv0 * c1);
                } else if (col < 96)  *(float2*)(g_s02 + (size_t)r0 * 32 + (col - 64)) = make_float2(c0, c1);
                else if (col < 112)   *(float2*)(g_s03 + (size_t)r0 * 16 + (col - 96)) = make_float2(c0, c1);
            }
            if (r1 < N_NODES) {
                if (col < 64) {
                    *(__half2*)(g_hs1h + (size_t)r1 * 64 + col) = __floats2half2_rn(dv1 * c2, dv1 * c3);
                } else if (col < 96)  *(float2*)(g_s02 + (size_t)r1 * 32 + (col - 64)) = make_float2(c2, c3);
                else if (col < 112)   *(float2*)(g_s03 + (size_t)r1 * 16 + (col - 96)) = make_float2(c2, c3);
            }
        }
    }
}

// ---------------- GEMM2 (mma.sync fp16): x1[100k,64] @ Wcat2[64,64] ----------------
#define G2_A 0
#define G2_B 16384
#define G2_TOTAL 24576

__global__ __launch_bounds__(256, 2) void k_gemm2_mma() {
    extern __shared__ __align__(1024) char smem[];
    uint32_t sb = smem_u32(smem);
    int tid = threadIdx.x, wid = tid >> 5, lane = tid & 31;
    int rowBase = blockIdx.x * 128;
    int mw = wid >> 1, nw = wid & 1;
    int g = lane >> 2, t4 = lane & 3;
    int lr = lane & 7, lts = lane >> 3;

    float c[2][4][4];
    #pragma unroll
    for (int a = 0; a < 2; a++)
        #pragma unroll
        for (int b = 0; b < 4; b++)
            #pragma unroll
            for (int d = 0; d < 4; d++) c[a][b][d] = 0.f;

    #pragma unroll
    for (int i = 0; i < 4; i++) {
        int gidx = tid + i * 256;
        int row = gidx >> 3, q = gidx & 7;
        int gr = rowBase + row;
        uint32_t off = SW128(row * 128 + q * 16);
        if (gr < N_NODES) {
            *(uint4*)(smem + G2_A + off) = *(const uint4*)((const char*)g_x1h + (size_t)gr * 128 + (size_t)q * 16);
        } else {
            *(uint4*)(smem + G2_A + off) = make_uint4(0, 0, 0, 0);
        }
    }
    #pragma unroll
    for (int i = 0; i < 2; i++) {
        int gidx = tid + i * 256;
        int n = gidx >> 3, q = gidx & 7;
        uint32_t off = SW128(n * 128 + q * 16);
        *(uint4*)(smem + G2_B + off) = *(const uint4*)((const char*)g_W2h + (size_t)n * 128 + (size_t)q * 16);
    }
    __syncthreads();

    #pragma unroll
    for (int ks = 0; ks < 4; ks++) {
        int k0 = ks * 16;
        uint32_t aF[2][4], bF[4][2];
        #pragma unroll
        for (int mt = 0; mt < 2; mt++) {
            int row = mw * 32 + mt * 16 + lr + ((lts & 1) << 3);
            int kk = k0 + ((lts >> 1) << 3);
            uint32_t off = SW128(row * 128 + kk * 2);
            ldsm_x4(sb + G2_A + off, aF[mt]);
        }
        {
            int n = nw * 32 + lts * 8 + lr;
            uint32_t offLo = SW128(n * 128 + k0 * 2);
            uint32_t offHi = SW128(n * 128 + (k0 + 8) * 2);
            uint32_t t0[4], t1[4];
            ldsm_x4(sb + G2_B + offLo, t0);
            ldsm_x4(sb + G2_B + offHi, t1);
            #pragma unroll
            for (int j = 0; j < 4; j++) { bF[j][0] = t0[j]; bF[j][1] = t1[j]; }
        }
        #pragma unroll
        for (int mt = 0; mt < 2; mt++)
            #pragma unroll
            for (int j = 0; j < 4; j++)
                mma16816h(c[mt][j], aF[mt], bF[j]);
    }

    #pragma unroll
    for (int mt = 0; mt < 2; mt++) {
        int r0 = rowBase + mw * 32 + mt * 16 + g;
        int r1 = r0 + 8;
        float dv0 = (r0 < N_NODES) ? g_dinv[r0] : 0.f;
        float dv1 = (r1 < N_NODES) ? g_dinv[r1] : 0.f;
        #pragma unroll
        for (int j = 0; j < 4; j++) {
            int col = nw * 32 + j * 8 + t4 * 2;
            float c0 = c[mt][j][0], c1 = c[mt][j][1];
            float c2 = c[mt][j][2], c3 = c[mt][j][3];
            if (r0 < N_NODES) {
                if (col < 32) {
                    *(__half2*)(g_hs2h + (size_t)r0 * 32 + col) = __floats2half2_rn(dv0 * c0, dv0 * c1);
                } else if (col < 48) *(float2*)(g_s13 + (size_t)r0 * 16 + (col - 32)) = make_float2(c0, c1);
            }
            if (r1 < N_NODES) {
                if (col < 32) {
                    *(__half2*)(g_hs2h + (size_t)r1 * 32 + col) = __floats2half2_rn(dv1 * c2, dv1 * c3);
                } else if (col < 48) *(float2*)(g_s13 + (size_t)r1 * 16 + (col - 32)) = make_float2(c2, c3);
            }
        }
    }
}

// ---------------- GEMM 3 (small): x2[100k,32] @ W3[32,16] ----------------
__global__ __launch_bounds__(256) void k_gemm3(const float* __restrict__ W3) {
    __shared__ float sW[32 * 16];
    int tid = threadIdx.x;
    sW[tid] = W3[tid];
    sW[tid + 256] = W3[tid + 256];
    __syncthreads();
    int gid = blockIdx.x * 256 + tid;
    int node = gid >> 4, cc = gid & 15;
    const __half2* xr = (const __half2*)(g_x2h + (size_t)node * 32);
    float acc = 0.f;
    #pragma unroll
    for (int k = 0; k < 16; k++) {
        float2 p = __half22float2(xr[k]);
        acc += p.x * sW[(2 * k) * 16 + cc] + p.y * sW[(2 * k + 1) * 16 + cc];
    }
    g_hs3h[gid] = __float2half(g_dinv[node] * acc);
}

// ---------------- shfl-free aggregation with fp16 pair-combine ----------------
// agg1: DIM=64 fp16 -> 8 uint4/row. 4 groups of 8 lanes; group walks every 4th edge.
__global__ __launch_bounds__(256) void k_agg1(const float* __restrict__ b1) {
    int wid = threadIdx.x >> 5, lane = threadIdx.x & 31;
    int node = blockIdx.x * 8 + wid;
    int oc = lane >> 3, fl = lane & 7;
    const uint4* hs = (const uint4*)g_hs1h;
    int beg = g_rowptr[node], end = g_rowptr[node + 1];
    float f[8] = {0.f, 0.f, 0.f, 0.f, 0.f, 0.f, 0.f, 0.f};
    if (oc == 0) acc_u4(f, hs[(size_t)node * 8 + fl]);   // self term (prescaled)
    int e = beg + oc;
    // quad: two fp16 pair-combines per iteration
    for (; e + 12 < end; e += 16) {
        int j0 = g_col[e];
        int j1 = g_col[e + 4];
        int j2 = g_col[e + 8];
        int j3 = g_col[e + 12];
        uint4 a = hs[(size_t)j0 * 8 + fl];
        uint4 b = hs[(size_t)j1 * 8 + fl];
        uint4 cc = hs[(size_t)j2 * 8 + fl];
        uint4 d = hs[(size_t)j3 * 8 + fl];
        acc_u4(f, hadd2_u4(a, b));
        acc_u4(f, hadd2_u4(cc, d));
    }
    for (; e + 4 < end; e += 8) {
        int j0 = g_col[e];
        int j1 = g_col[e + 4];
        uint4 a = hs[(size_t)j0 * 8 + fl];
        uint4 b = hs[(size_t)j1 * 8 + fl];
        acc_u4(f, hadd2_u4(a, b));
    }
    if (e < end) acc_u4(f, hs[(size_t)g_col[e] * 8 + fl]);
    #pragma unroll
    for (int i = 0; i < 8; i++) {
        f[i] += __shfl_xor_sync(0xffffffffu, f[i], 8);
        f[i] += __shfl_xor_sync(0xffffffffu, f[i], 16);
    }
    if (oc == 0) {
        float dv = g_dinv[node];
        float4 b0 = ((const float4*)b1)[2 * fl];
        float4 b4 = ((const float4*)b1)[2 * fl + 1];
        float o[8];
        o[0] = fmaxf(dv * f[0] + b0.x, 0.f); o[1] = fmaxf(dv * f[1] + b0.y, 0.f);
        o[2] = fmaxf(dv * f[2] + b0.z, 0.f); o[3] = fmaxf(dv * f[3] + b0.w, 0.f);
        o[4] = fmaxf(dv * f[4] + b4.x, 0.f); o[5] = fmaxf(dv * f[5] + b4.y, 0.f);
        o[6] = fmaxf(dv * f[6] + b4.z, 0.f); o[7] = fmaxf(dv * f[7] + b4.w, 0.f);
        uint4 hv;
        uint32_t* hp = (uint32_t*)&hv;
        #pragma unroll
        for (int q = 0; q < 4; q++) {
            __half2 p = __floats2half2_rn(o[2 * q], o[2 * q + 1]);
            hp[q] = *reinterpret_cast<uint32_t*>(&p);
        }
        ((uint4*)g_x1h)[(size_t)node * 8 + fl] = hv;
    }
}

// agg2: DIM=32 fp16 -> 4 uint4/row. 8 groups of 4 lanes, stride 8; fp16 pair e,e+8.
__global__ __launch_bounds__(256) void k_agg2(const float* __restrict__ b2,
                                              const float* __restrict__ bs02) {
    int wid = threadIdx.x >> 5, lane = threadIdx.x & 31;
    int node = blockIdx.x * 8 + wid;
    int oc = lane >> 2, fl = lane & 3;
    const uint4* hs = (const uint4*)g_hs2h;
    int beg = g_rowptr[node], end = g_rowptr[node + 1];
    float f[8] = {0.f, 0.f, 0.f, 0.f, 0.f, 0.f, 0.f, 0.f};
    if (oc == 0) acc_u4(f, hs[(size_t)node * 4 + fl]);
    int e = beg + oc;
    for (; e + 8 < end; e += 16) {
        int j0 = g_col[e];
        int j1 = g_col[e + 8];
        uint4 a = hs[(size_t)j0 * 4 + fl];
        uint4 b = hs[(size_t)j1 * 4 + fl];
        acc_u4(f, hadd2_u4(a, b));
    }
    if (e < end) acc_u4(f, hs[(size_t)g_col[e] * 4 + fl]);
    #pragma unroll
    for (int i = 0; i < 8; i++) {
        f[i] += __shfl_xor_sync(0xffffffffu, f[i], 4);
        f[i] += __shfl_xor_sync(0xffffffffu, f[i], 8);
        f[i] += __shfl_xor_sync(0xffffffffu, f[i], 16);
    }
    if (oc == 0) {
        float dv = g_dinv[node];
        float4 b0 = ((const float4*)b2)[2 * fl];
        float4 b4 = ((const float4*)b2)[2 * fl + 1];
        float4 sb0 = ((const float4*)bs02)[2 * fl];
        float4 sb4 = ((const float4*)bs02)[2 * fl + 1];
        float4 s0 = ((const float4*)g_s02)[(size_t)node * 8 + 2 * fl];
        float4 s4 = ((const float4*)g_s02)[(size_t)node * 8 + 2 * fl + 1];
        float o[8];
        o[0] = fmaxf(dv * f[0] + b0.x + s0.x + sb0.x, 0.f);
        o[1] = fmaxf(dv * f[1] + b0.y + s0.y + sb0.y, 0.f);
        o[2] = fmaxf(dv * f[2] + b0.z + s0.z + sb0.z, 0.f);
        o[3] = fmaxf(dv * f[3] + b0.w + s0.w + sb0.w, 0.f);
        o[4] = fmaxf(dv * f[4] + b4.x + s4.x + sb4.x, 0.f);
        o[5] = fmaxf(dv * f[5] + b4.y + s4.y + sb4.y, 0.f);
        o[6] = fmaxf(dv * f[6] + b4.z + s4.z + sb4.z, 0.f);
        o[7] = fmaxf(dv * f[7] + b4.w + s4.w + sb4.w, 0.f);
        uint4 hv;
        uint32_t* hp = (uint32_t*)&hv;
        #pragma unroll
        for (int q = 0; q < 4; q++) {
            __half2 p = __floats2half2_rn(o[2 * q], o[2 * q + 1]);
            hp[q] = *reinterpret_cast<uint32_t*>(&p);
        }
        ((uint4*)g_x2h)[(size_t)node * 4 + fl] = hv;
    }
}

// agg3: DIM=16 fp16 -> 2 uint4/row. 16 groups of 2 lanes, stride 16; fp16 pair e,e+16.
__global__ __launch_bounds__(256) void k_agg3(const float* __restrict__ b3,
                                              const float* __restrict__ bs03,
                                              const float* __restrict__ bs13,
                                              const float* __restrict__ Wout,
                                              const float* __restrict__ bout,
                                              float* __restrict__ out) {
    int wid = threadIdx.x >> 5, lane = threadIdx.x & 31;
    int node = blockIdx.x * 8 + wid;
    int oc = lane >> 1, fl = lane & 1;
    const uint4* hs = (const uint4*)g_hs3h;
    int beg = g_rowptr[node], end = g_rowptr[node + 1];
    float f[8] = {0.f, 0.f, 0.f, 0.f, 0.f, 0.f, 0.f, 0.f};
    if (oc == 0) acc_u4(f, hs[(size_t)node * 2 + fl]);
    int e = beg + oc;
    for (; e + 16 < end; e += 32) {
        int j0 = g_col[e];
        int j1 = g_col[e + 16];
        uint4 a = hs[(size_t)j0 * 2 + fl];
        uint4 b = hs[(size_t)j1 * 2 + fl];
        acc_u4(f, hadd2_u4(a, b));
    }
    if (e < end) acc_u4(f, hs[(size_t)g_col[e] * 2 + fl]);
    #pragma unroll
    for (int i = 0; i < 8; i++) {
        f[i] += __shfl_xor_sync(0xffffffffu, f[i], 2);
        f[i] += __shfl_xor_sync(0xffffffffu, f[i], 4);
        f[i] += __shfl_xor_sync(0xffffffffu, f[i], 8);
        f[i] += __shfl_xor_sync(0xffffffffu, f[i], 16);
    }
    float dv = g_dinv[node];
    float4 b0 = ((const float4*)b3)[2 * fl];
    float4 b4 = ((const float4*)b3)[2 * fl + 1];
    float4 q0 = ((const float4*)bs03)[2 * fl];
    float4 q4 = ((const float4*)bs03)[2 * fl + 1];
    float4 r0 = ((const float4*)bs13)[2 * fl];
    float4 r4 = ((const float4*)bs13)[2 * fl + 1];
    float4 s0 = ((const float4*)g_s03)[(size_t)node * 4 + 2 * fl];
    float4 s4 = ((const float4*)g_s03)[(size_t)node * 4 + 2 * fl + 1];
    float4 u0 = ((const float4*)g_s13)[(size_t)node * 4 + 2 * fl];
    float4 u4 = ((const float4*)g_s13)[(size_t)node * 4 + 2 * fl + 1];
    float4 w0 = ((const float4*)Wout)[2 * fl];
    float4 w4 = ((const float4*)Wout)[2 * fl + 1];
    float t0 = fmaxf(dv * f[0] + b0.x + s0.x + q0.x + u0.x + r0.x, 0.f);
    float t1 = fmaxf(dv * f[1] + b0.y + s0.y + q0.y + u0.y + r0.y, 0.f);
    float t2 = fmaxf(dv * f[2] + b0.z + s0.z + q0.z + u0.z + r0.z, 0.f);
    float t3 = fmaxf(dv * f[3] + b0.w + s0.w + q0.w + u0.w + r0.w, 0.f);
    float t4v = fmaxf(dv * f[4] + b4.x + s4.x + q4.x + u4.x + r4.x, 0.f);
    float t5 = fmaxf(dv * f[5] + b4.y + s4.y + q4.y + u4.y + r4.y, 0.f);
    float t6 = fmaxf(dv * f[6] + b4.z + s4.z + q4.z + u4.z + r4.z, 0.f);
    float t7 = fmaxf(dv * f[7] + b4.w + s4.w + q4.w + u4.w + r4.w, 0.f);
    float v = t0 * w0.x + t1 * w0.y + t2 * w0.z + t3 * w0.w
            + t4v * w4.x + t5 * w4.y + t6 * w4.z + t7 * w4.w;
    v += __shfl_xor_sync(0xffffffffu, v, 1);
    if (lane == 0) out[node] = 1.f / (1.f + __expf(-(v + bout[0])));
}

// ---------------- launch ----------------
extern "C" void kernel_launch(void* const* d_in, const int* in_sizes, int n_in,
                              void* d_out, int out_size) {
    const float* x    = (const float*)d_in[0];
    const int*   ei   = (const int*)d_in[1];
    const float* W1   = (const float*)d_in[2];
    const float* b1   = (const float*)d_in[3];
    const float* W2   = (const float*)d_in[4];
    const float* b2   = (const float*)d_in[5];
    const float* W3   = (const float*)d_in[6];
    const float* b3   = (const float*)d_in[7];
    const float* Ws02 = (const float*)d_in[8];
    const float* bs02 = (const float*)d_in[9];
    const float* Ws03 = (const float*)d_in[10];
    const float* bs03 = (const float*)d_in[11];
    const float* Ws13 = (const float*)d_in[12];
    const float* bs13 = (const float*)d_in[13];
    const float* Wout = (const float*)d_in[14];
    const float* bout = (const float*)d_in[15];
    float* out = (float*)d_out;

    const int* src = ei;
    const int* dst = ei + N_EDGES;

    cudaFuncSetAttribute(k_gemm1_mma, cudaFuncAttributeMaxDynamicSharedMemorySize, G1_TOTAL);
    cudaFuncSetAttribute(k_gemm2_mma, cudaFuncAttributeMaxDynamicSharedMemorySize, G2_TOTAL);

    void* p = nullptr;
    cudaGetSymbolAddress(&p, g_cnt);
    cudaMemsetAsync(p, 0, N_NODES * sizeof(int));
    cudaGetSymbolAddress(&p, g_bar);
    cudaMemsetAsync(p, 0, sizeof(int));

    k_csr_a<<<CSR_BLOCKS, 256>>>(dst);                              // 1
    k_packs<<<(128 * 256 + 64 * 64 + 255) / 256, 256>>>(W1, Ws02, Ws03, W2, Ws13); // 2
    k_gemm1_mma<<<(N_NODES + 127) / 128, 256, G1_TOTAL>>>(x);       // 3
    k_fill<<<N_EDGES / 4 / 256, 256>>>(src, dst);                   // 4 (profiled)
    k_agg1<<<12500, 256>>>(b1);                                     // 5
    k_gemm2_mma<<<(N_NODES + 127) / 128, 256, G2_TOTAL>>>();        // 6
    k_agg2<<<12500, 256>>>(b2, bs02);                               // 7
    k_gemm3<<<(N_NODES * 16 + 255) / 256, 256>>>(W3);               // 8
    k_agg3<<<12500, 256>>>(b3, bs03, bs13, Wout, bout, out);        // 9
}